// round 8
// baseline (speedup 1.0000x reference)
#include <cuda_runtime.h>
#include <cuda_bf16.h>
#include <cstdint>

#define T_TOK 32768
#define H_DIM 2048
#define I_DIM 768

using bf16 = __nv_bfloat16;

// ---------------- static device scratch ------------------------------------
__device__ bf16 g_Ahi[(size_t)T_TOK * H_DIM];
__device__ bf16 g_Alo[(size_t)T_TOK * H_DIM];
__device__ bf16 g_Wgu_hi[(size_t)2 * I_DIM * H_DIM];   // w_gate_up^T  [2I, H]
__device__ bf16 g_Wgu_lo[(size_t)2 * I_DIM * H_DIM];
__device__ bf16 g_Wd_hi[(size_t)H_DIM * I_DIM];        // w_down^T     [H, I]
__device__ bf16 g_Wd_lo[(size_t)H_DIM * I_DIM];
__device__ bf16 g_Xhi[(size_t)T_TOK * I_DIM];          // silu(g)*u    [T, I]
__device__ bf16 g_Xlo[(size_t)T_TOK * I_DIM];

// ---------------- helpers ----------------------------------------------------
__device__ __forceinline__ uint32_t smem_u32(const void* p) {
    return (uint32_t)__cvta_generic_to_shared(p);
}
__device__ __forceinline__ void cp16(uint32_t dst, const void* src) {
    asm volatile("cp.async.cg.shared.global [%0], [%1], 16;" :: "r"(dst), "l"(src));
}
__device__ __forceinline__ void cp_commit() {
    asm volatile("cp.async.commit_group;" ::: "memory");
}
template <int N>
__device__ __forceinline__ void cp_wait() {
    asm volatile("cp.async.wait_group %0;" :: "n"(N) : "memory");
}
__device__ __forceinline__ void ldsm_x4(uint32_t* r, uint32_t addr) {
    asm volatile("ldmatrix.sync.aligned.m8n8.x4.shared.b16 {%0,%1,%2,%3}, [%4];"
                 : "=r"(r[0]), "=r"(r[1]), "=r"(r[2]), "=r"(r[3]) : "r"(addr));
}
__device__ __forceinline__ void mma16816(float* d, const uint32_t* a,
                                         uint32_t b0, uint32_t b1) {
    asm volatile(
        "mma.sync.aligned.m16n8k16.row.col.f32.bf16.bf16.f32 "
        "{%0,%1,%2,%3}, {%4,%5,%6,%7}, {%8,%9}, {%0,%1,%2,%3};"
        : "+f"(d[0]), "+f"(d[1]), "+f"(d[2]), "+f"(d[3])
        : "r"(a[0]), "r"(a[1]), "r"(a[2]), "r"(a[3]), "r"(b0), "r"(b1));
}
__device__ __forceinline__ uint32_t pk2(bf16 a, bf16 b) {
    __nv_bfloat162 t; t.x = a; t.y = b;
    return *reinterpret_cast<uint32_t*>(&t);
}
__device__ __forceinline__ void split1(float a, bf16& h, bf16& l) {
    h = __float2bfloat16_rn(a);
    l = __float2bfloat16_rn(a - __bfloat162float(h));
}

// SMEM stage layout (BK=32, rows padded to 80B -> conflict-free ldmatrix):
//   Ahi @0 (128x80=10240), Alo @10240, Bhi @20480, Blo @30720
#define ROWB        80
#define ARR_BYTES   10240
#define STAGE_BYTES 40960
#define NSTAGE      4
#define SMEM_BYTES  (NSTAGE * STAGE_BYTES)

// ============================================================================
// GEMM1: hidden[T,H] x Wgu^T[2I,H] -> silu(gate)*up -> Xhi/Xlo [T,I]
// CTA: 512 threads, 16 warps (4m x 4n). Tile 128 tokens x 64 I-cols (g+u).
// Warp tile: 32(M) x 16(N), both gate and up accumulators.
// ============================================================================
__device__ __forceinline__ void g1_load_stage(
    uint32_t SB, int k0, int bm, int nt,
    const bf16* __restrict__ Ahi, const bf16* __restrict__ Alo,
    const bf16* __restrict__ Wh,  const bf16* __restrict__ Wl, int tid)
{
    int row = tid >> 2, kc = tid & 3;             // 128 rows x 4 chunks
    {   // A tile (hi + lo)
        uint32_t d = SB + row * ROWB + kc * 16;
        size_t gof = (size_t)(bm + row) * H_DIM + k0 + kc * 8;
        cp16(d,             Ahi + gof);
        cp16(d + ARR_BYTES, Alo + gof);
    }
    {   // B tile: 64 gate rows + 64 up rows (hi + lo)
        int gr = (row < 64) ? (nt * 64 + row) : (I_DIM + nt * 64 + row - 64);
        uint32_t d = SB + 20480 + row * ROWB + kc * 16;
        size_t gof = (size_t)gr * H_DIM + k0 + kc * 8;
        cp16(d,             Wh + gof);
        cp16(d + ARR_BYTES, Wl + gof);
    }
}

__global__ __launch_bounds__(512, 1)
void gemm1_k(const bf16* __restrict__ Ahi, const bf16* __restrict__ Alo,
             const bf16* __restrict__ Wh,  const bf16* __restrict__ Wl,
             bf16* __restrict__ Xhi, bf16* __restrict__ Xlo)
{
    extern __shared__ char smem[];
    const uint32_t sb = smem_u32(smem);
    const int tid = threadIdx.x, wid = tid >> 5, lane = tid & 31;
    const int warp_m = wid & 3, warp_n = wid >> 2;
    const int nt = blockIdx.x;                  // 0..11 (64 I-cols each)
    const int bm = blockIdx.y * 128;
    const int NITER = H_DIM / 32;               // 64

    float accg[2][2][4], accu[2][2][4];
#pragma unroll
    for (int mi = 0; mi < 2; mi++)
#pragma unroll
        for (int ni = 0; ni < 2; ni++)
#pragma unroll
            for (int v = 0; v < 4; v++) { accg[mi][ni][v] = 0.f; accu[mi][ni][v] = 0.f; }

    g1_load_stage(sb, 0, bm, nt, Ahi, Alo, Wh, Wl, tid); cp_commit();
    g1_load_stage(sb + STAGE_BYTES, 32, bm, nt, Ahi, Alo, Wh, Wl, tid); cp_commit();
    g1_load_stage(sb + 2 * STAGE_BYTES, 64, bm, nt, Ahi, Alo, Wh, Wl, tid); cp_commit();

    const int arow = lane & 15;
    const int acol = (lane >> 4) * 16;
    const int brow = (lane & 7) + ((lane >> 4) << 3);
    const int bcol = ((lane >> 3) & 1) * 16;

    for (int it = 0; it < NITER; ++it) {
        cp_wait<2>();
        __syncthreads();     // single barrier: stage being overwritten consumed @ it-1
        if (it + 3 < NITER) {
            g1_load_stage(sb + ((it + 3) & 3) * STAGE_BYTES, (it + 3) * 32,
                          bm, nt, Ahi, Alo, Wh, Wl, tid);
        }
        cp_commit();

        uint32_t SB = sb + (it & 3) * STAGE_BYTES;
#pragma unroll
        for (int ks = 0; ks < 2; ks++) {
            uint32_t rb = SB + 20480 + (warp_n * 16 + brow) * ROWB + ks * 32 + bcol;
            uint32_t bgh[4], bgl[4], buh[4], bul[4];
            ldsm_x4(bgh, rb);
            ldsm_x4(bgl, rb + ARR_BYTES);
            ldsm_x4(buh, rb + 64 * ROWB);
            ldsm_x4(bul, rb + 64 * ROWB + ARR_BYTES);

            uint32_t ah[2][4], al[2][4];
#pragma unroll
            for (int mi = 0; mi < 2; mi++) {
                uint32_t ra = SB + (warp_m * 32 + mi * 16 + arow) * ROWB + ks * 32 + acol;
                ldsm_x4(ah[mi], ra);
                ldsm_x4(al[mi], ra + ARR_BYTES);
            }
            // pass 1: hi * B_hi
#pragma unroll
            for (int mi = 0; mi < 2; mi++)
#pragma unroll
                for (int ni = 0; ni < 2; ni++) {
                    mma16816(accg[mi][ni], ah[mi], bgh[ni*2], bgh[ni*2+1]);
                    mma16816(accu[mi][ni], ah[mi], buh[ni*2], buh[ni*2+1]);
                }
            // pass 2: hi * B_lo
#pragma unroll
            for (int mi = 0; mi < 2; mi++)
#pragma unroll
                for (int ni = 0; ni < 2; ni++) {
                    mma16816(accg[mi][ni], ah[mi], bgl[ni*2], bgl[ni*2+1]);
                    mma16816(accu[mi][ni], ah[mi], bul[ni*2], bul[ni*2+1]);
                }
            // pass 3: lo * B_hi
#pragma unroll
            for (int mi = 0; mi < 2; mi++)
#pragma unroll
                for (int ni = 0; ni < 2; ni++) {
                    mma16816(accg[mi][ni], al[mi], bgh[ni*2], bgh[ni*2+1]);
                    mma16816(accu[mi][ni], al[mi], buh[ni*2], buh[ni*2+1]);
                }
        }
    }

    // epilogue: silu(gate)*up, split, store packed pairs
    const int g = lane >> 2, t = lane & 3;
#pragma unroll
    for (int mi = 0; mi < 2; mi++)
#pragma unroll
        for (int ni = 0; ni < 2; ni++) {
            int col = nt * 64 + warp_n * 16 + ni * 8 + t * 2;
            int row0 = bm + warp_m * 32 + mi * 16 + g;
#pragma unroll
            for (int h = 0; h < 2; h++) {
                int row = row0 + h * 8;
                float g0 = accg[mi][ni][h*2],   g1 = accg[mi][ni][h*2+1];
                float u0 = accu[mi][ni][h*2],   u1 = accu[mi][ni][h*2+1];
                float x0 = u0 * g0 / (1.0f + __expf(-g0));
                float x1 = u1 * g1 / (1.0f + __expf(-g1));
                bf16 h0, l0, h1, l1;
                split1(x0, h0, l0); split1(x1, h1, l1);
                size_t o = (size_t)row * I_DIM + col;
                *reinterpret_cast<uint32_t*>(Xhi + o) = pk2(h0, h1);
                *reinterpret_cast<uint32_t*>(Xlo + o) = pk2(l0, l1);
            }
        }
}

// ============================================================================
// GEMM2: X[T,I] x Wd^T[H,I] -> out[T,H] fp32
// CTA: 512 threads, 16 warps (4m x 4n). Tile 128 tokens x 128 H-cols.
// Warp tile: 32(M) x 32(N).
// ============================================================================
__device__ __forceinline__ void g2_load_stage(
    uint32_t SB, int k0, int bm, int bn,
    const bf16* __restrict__ Xh, const bf16* __restrict__ Xl,
    const bf16* __restrict__ Dh, const bf16* __restrict__ Dl, int tid)
{
    int row = tid >> 2, kc = tid & 3;
    {
        uint32_t d = SB + row * ROWB + kc * 16;
        size_t gof = (size_t)(bm + row) * I_DIM + k0 + kc * 8;
        cp16(d,             Xh + gof);
        cp16(d + ARR_BYTES, Xl + gof);
    }
    {
        uint32_t d = SB + 20480 + row * ROWB + kc * 16;
        size_t gof = (size_t)(bn + row) * I_DIM + k0 + kc * 8;
        cp16(d,             Dh + gof);
        cp16(d + ARR_BYTES, Dl + gof);
    }
}

__global__ __launch_bounds__(512, 1)
void gemm2_k(const bf16* __restrict__ Xh, const bf16* __restrict__ Xl,
             const bf16* __restrict__ Dh, const bf16* __restrict__ Dl,
             float* __restrict__ out)
{
    extern __shared__ char smem[];
    const uint32_t sb = smem_u32(smem);
    const int tid = threadIdx.x, wid = tid >> 5, lane = tid & 31;
    const int warp_m = wid & 3, warp_n = wid >> 2;
    const int bn = blockIdx.x * 128;
    const int bm = blockIdx.y * 128;
    const int NITER = I_DIM / 32;               // 24

    float acc[2][4][4];
#pragma unroll
    for (int mi = 0; mi < 2; mi++)
#pragma unroll
        for (int ni = 0; ni < 4; ni++)
#pragma unroll
            for (int v = 0; v < 4; v++) acc[mi][ni][v] = 0.f;

    g2_load_stage(sb, 0, bm, bn, Xh, Xl, Dh, Dl, tid); cp_commit();
    g2_load_stage(sb + STAGE_BYTES, 32, bm, bn, Xh, Xl, Dh, Dl, tid); cp_commit();
    g2_load_stage(sb + 2 * STAGE_BYTES, 64, bm, bn, Xh, Xl, Dh, Dl, tid); cp_commit();

    const int arow = lane & 15;
    const int acol = (lane >> 4) * 16;
    const int brow = (lane & 7) + ((lane >> 4) << 3);
    const int bcol = ((lane >> 3) & 1) * 16;

    for (int it = 0; it < NITER; ++it) {
        cp_wait<2>();
        __syncthreads();
        if (it + 3 < NITER) {
            g2_load_stage(sb + ((it + 3) & 3) * STAGE_BYTES, (it + 3) * 32,
                          bm, bn, Xh, Xl, Dh, Dl, tid);
        }
        cp_commit();

        uint32_t SB = sb + (it & 3) * STAGE_BYTES;
#pragma unroll
        for (int ks = 0; ks < 2; ks++) {
            uint32_t bh[8], bl[8];
#pragma unroll
            for (int bq = 0; bq < 2; bq++) {
                uint32_t rb = SB + 20480 + (warp_n * 32 + bq * 16 + brow) * ROWB + ks * 32 + bcol;
                ldsm_x4(&bh[bq*4], rb);
                ldsm_x4(&bl[bq*4], rb + ARR_BYTES);
            }
            uint32_t ah[2][4], al[2][4];
#pragma unroll
            for (int mi = 0; mi < 2; mi++) {
                uint32_t ra = SB + (warp_m * 32 + mi * 16 + arow) * ROWB + ks * 32 + acol;
                ldsm_x4(ah[mi], ra);
                ldsm_x4(al[mi], ra + ARR_BYTES);
            }
            // pass 1: hi * B_hi
#pragma unroll
            for (int mi = 0; mi < 2; mi++)
#pragma unroll
                for (int ni = 0; ni < 4; ni++)
                    mma16816(acc[mi][ni], ah[mi], bh[ni*2], bh[ni*2+1]);
            // pass 2: hi * B_lo
#pragma unroll
            for (int mi = 0; mi < 2; mi++)
#pragma unroll
                for (int ni = 0; ni < 4; ni++)
                    mma16816(acc[mi][ni], ah[mi], bl[ni*2], bl[ni*2+1]);
            // pass 3: lo * B_hi
#pragma unroll
            for (int mi = 0; mi < 2; mi++)
#pragma unroll
                for (int ni = 0; ni < 4; ni++)
                    mma16816(acc[mi][ni], al[mi], bh[ni*2], bh[ni*2+1]);
        }
    }

    const int g = lane >> 2, t = lane & 3;
#pragma unroll
    for (int mi = 0; mi < 2; mi++)
#pragma unroll
        for (int ni = 0; ni < 4; ni++) {
            int col = bn + warp_n * 32 + ni * 8 + t * 2;
            int row0 = bm + warp_m * 32 + mi * 16 + g;
            float2 v0 = make_float2(acc[mi][ni][0], acc[mi][ni][1]);
            float2 v1 = make_float2(acc[mi][ni][2], acc[mi][ni][3]);
            *reinterpret_cast<float2*>(out + (size_t)row0 * H_DIM + col) = v0;
            *reinterpret_cast<float2*>(out + (size_t)(row0 + 8) * H_DIM + col) = v1;
        }
}

// ---------------- prep kernels ----------------------------------------------
__global__ void split_hidden_k(const float* __restrict__ in,
                               bf16* __restrict__ hi, bf16* __restrict__ lo)
{
    size_t i = (size_t)blockIdx.x * blockDim.x + threadIdx.x;
    float4 v = reinterpret_cast<const float4*>(in)[i];
    bf16 h0, l0, h1, l1, h2, l2, h3, l3;
    split1(v.x, h0, l0); split1(v.y, h1, l1);
    split1(v.z, h2, l2); split1(v.w, h3, l3);
    uint2 ph; ph.x = pk2(h0, h1); ph.y = pk2(h2, h3);
    uint2 pl; pl.x = pk2(l0, l1); pl.y = pk2(l2, l3);
    reinterpret_cast<uint2*>(hi)[i] = ph;
    reinterpret_cast<uint2*>(lo)[i] = pl;
}

__global__ void transpose_split_k(const float* __restrict__ in,
                                  bf16* __restrict__ ohi, bf16* __restrict__ olo,
                                  int R, int C)
{
    __shared__ float t[32][33];
    int bx = blockIdx.x * 32, by = blockIdx.y * 32;
    int tx = threadIdx.x, ty = threadIdx.y;
#pragma unroll
    for (int j = 0; j < 32; j += 8)
        t[ty + j][tx] = in[(size_t)(by + ty + j) * C + bx + tx];
    __syncthreads();
#pragma unroll
    for (int j = 0; j < 32; j += 8) {
        float a = t[tx][ty + j];
        bf16 h, l; split1(a, h, l);
        size_t o = (size_t)(bx + ty + j) * R + by + tx;
        ohi[o] = h; olo[o] = l;
    }
}

// ---------------- host ------------------------------------------------------
extern "C" void kernel_launch(void* const* d_in, const int* in_sizes, int n_in,
                              void* d_out, int out_size)
{
    const float* hidden = (const float*)d_in[0];   // [T, H]
    const float* wgu    = (const float*)d_in[1];   // [H, 2I]
    const float* wd     = (const float*)d_in[2];   // [I, H]
    float* out = (float*)d_out;                    // [T, H]

    bf16 *Ahi, *Alo, *Wh, *Wl, *Dh, *Dl, *Xh, *Xl;
    cudaGetSymbolAddress((void**)&Ahi, g_Ahi);
    cudaGetSymbolAddress((void**)&Alo, g_Alo);
    cudaGetSymbolAddress((void**)&Wh,  g_Wgu_hi);
    cudaGetSymbolAddress((void**)&Wl,  g_Wgu_lo);
    cudaGetSymbolAddress((void**)&Dh,  g_Wd_hi);
    cudaGetSymbolAddress((void**)&Dl,  g_Wd_lo);
    cudaGetSymbolAddress((void**)&Xh,  g_Xhi);
    cudaGetSymbolAddress((void**)&Xl,  g_Xlo);

    cudaFuncSetAttribute(gemm1_k, cudaFuncAttributeMaxDynamicSharedMemorySize, SMEM_BYTES);
    cudaFuncSetAttribute(gemm2_k, cudaFuncAttributeMaxDynamicSharedMemorySize, SMEM_BYTES);

    split_hidden_k<<<(int)(((size_t)T_TOK * H_DIM / 4) / 256), 256>>>(hidden, Ahi, Alo);
    transpose_split_k<<<dim3(2 * I_DIM / 32, H_DIM / 32), dim3(32, 8)>>>(wgu, Wh, Wl, H_DIM, 2 * I_DIM);
    transpose_split_k<<<dim3(H_DIM / 32, I_DIM / 32), dim3(32, 8)>>>(wd, Dh, Dl, I_DIM, H_DIM);

    gemm1_k<<<dim3(I_DIM / 64, T_TOK / 128), 512, SMEM_BYTES>>>(Ahi, Alo, Wh, Wl, Xh, Xl);
    gemm2_k<<<dim3(H_DIM / 128, T_TOK / 128), 512, SMEM_BYTES>>>(Xh, Xl, Dh, Dl, out);
}

// round 9
// speedup vs baseline: 1.0902x; 1.0902x over previous
#include <cuda_runtime.h>
#include <cuda_bf16.h>
#include <cstdint>

#define T_TOK 32768
#define H_DIM 2048
#define I_DIM 768

using bf16 = __nv_bfloat16;

// ---------------- static device scratch ------------------------------------
__device__ bf16 g_Ahi[(size_t)T_TOK * H_DIM];
__device__ bf16 g_Alo[(size_t)T_TOK * H_DIM];
__device__ bf16 g_Wgu_hi[(size_t)2 * I_DIM * H_DIM];   // w_gate_up^T  [2I, H]
__device__ bf16 g_Wgu_lo[(size_t)2 * I_DIM * H_DIM];
__device__ bf16 g_Wd_hi[(size_t)H_DIM * I_DIM];        // w_down^T     [H, I]
__device__ bf16 g_Wd_lo[(size_t)H_DIM * I_DIM];
__device__ bf16 g_Xhi[(size_t)T_TOK * I_DIM];          // silu(g)*u    [T, I]
__device__ bf16 g_Xlo[(size_t)T_TOK * I_DIM];

// ---------------- helpers ----------------------------------------------------
__device__ __forceinline__ uint32_t smem_u32(const void* p) {
    return (uint32_t)__cvta_generic_to_shared(p);
}
__device__ __forceinline__ void cp16(uint32_t dst, const void* src) {
    asm volatile("cp.async.cg.shared.global [%0], [%1], 16;" :: "r"(dst), "l"(src));
}
__device__ __forceinline__ void cp_commit() {
    asm volatile("cp.async.commit_group;" ::: "memory");
}
template <int N>
__device__ __forceinline__ void cp_wait() {
    asm volatile("cp.async.wait_group %0;" :: "n"(N) : "memory");
}
__device__ __forceinline__ void ldsm_x4(uint32_t* r, uint32_t addr) {
    asm volatile("ldmatrix.sync.aligned.m8n8.x4.shared.b16 {%0,%1,%2,%3}, [%4];"
                 : "=r"(r[0]), "=r"(r[1]), "=r"(r[2]), "=r"(r[3]) : "r"(addr));
}
__device__ __forceinline__ void mma16816(float* d, const uint32_t* a,
                                         uint32_t b0, uint32_t b1) {
    asm volatile(
        "mma.sync.aligned.m16n8k16.row.col.f32.bf16.bf16.f32 "
        "{%0,%1,%2,%3}, {%4,%5,%6,%7}, {%8,%9}, {%0,%1,%2,%3};"
        : "+f"(d[0]), "+f"(d[1]), "+f"(d[2]), "+f"(d[3])
        : "r"(a[0]), "r"(a[1]), "r"(a[2]), "r"(a[3]), "r"(b0), "r"(b1));
}
__device__ __forceinline__ uint32_t pk2(bf16 a, bf16 b) {
    __nv_bfloat162 t; t.x = a; t.y = b;
    return *reinterpret_cast<uint32_t*>(&t);
}
__device__ __forceinline__ void split1(float a, bf16& h, bf16& l) {
    h = __float2bfloat16_rn(a);
    l = __float2bfloat16_rn(a - __bfloat162float(h));
}

// SMEM stage layout (BK=32): each row = [hi 64B | lo 64B | 16B pad], stride 144B.
// ldmatrix 8-row bank starts: (r*36)%32 words = {0,4,8,...,28} -> conflict-free.
//   A tile rows 0..127 @0, B tile rows 0..127 @18432
#define ROWB        144
#define LO_OFF      64
#define B_OFF       18432
#define STAGE_BYTES 36864
#define NSTAGE      3
#define SMEM_BYTES  (NSTAGE * STAGE_BYTES)

// ============================================================================
// GEMM1: hidden[T,H] x Wgu^T[2I,H] -> silu(gate)*up -> Xhi/Xlo [T,I]
// CTA: 256 threads, 8 warps (2m x 4n). Tile 128 tokens x 64 I-cols (g+u).
// Warp tile: 64(M) x 16(N), gate and up accumulators.
// ============================================================================
__device__ __forceinline__ void g1_load_stage(
    uint32_t SB, int k0, int bm, int nt,
    const bf16* __restrict__ Ahi, const bf16* __restrict__ Alo,
    const bf16* __restrict__ Wh,  const bf16* __restrict__ Wl, int tid)
{
#pragma unroll
    for (int c = tid; c < 512; c += 256) {            // A: 128 rows x 4 chunks
        int row = c >> 2, kc = c & 3;                 // coalesced 64B per 4 threads
        uint32_t d = SB + row * ROWB + kc * 16;
        size_t gof = (size_t)(bm + row) * H_DIM + k0 + kc * 8;
        cp16(d,          Ahi + gof);
        cp16(d + LO_OFF, Alo + gof);
    }
#pragma unroll
    for (int c = tid; c < 512; c += 256) {            // B: 64 gate + 64 up rows
        int row = c >> 2, kc = c & 3;
        int gr = (row < 64) ? (nt * 64 + row) : (I_DIM + nt * 64 + row - 64);
        uint32_t d = SB + B_OFF + row * ROWB + kc * 16;
        size_t gof = (size_t)gr * H_DIM + k0 + kc * 8;
        cp16(d,          Wh + gof);
        cp16(d + LO_OFF, Wl + gof);
    }
}

__global__ __launch_bounds__(256, 2)
void gemm1_k(const bf16* __restrict__ Ahi, const bf16* __restrict__ Alo,
             const bf16* __restrict__ Wh,  const bf16* __restrict__ Wl,
             bf16* __restrict__ Xhi, bf16* __restrict__ Xlo)
{
    extern __shared__ char smem[];
    const uint32_t sb = smem_u32(smem);
    const int tid = threadIdx.x, wid = tid >> 5, lane = tid & 31;
    const int warp_m = wid & 1, warp_n = wid >> 1;
    const int nt = blockIdx.x;                  // 0..11 (64 I-cols each)
    const int bm = blockIdx.y * 128;
    const int NITER = H_DIM / 32;               // 64

    float accg[4][2][4], accu[4][2][4];
#pragma unroll
    for (int mi = 0; mi < 4; mi++)
#pragma unroll
        for (int ni = 0; ni < 2; ni++)
#pragma unroll
            for (int v = 0; v < 4; v++) { accg[mi][ni][v] = 0.f; accu[mi][ni][v] = 0.f; }

    // prologue: prefetch distance 2
    g1_load_stage(sb, 0, bm, nt, Ahi, Alo, Wh, Wl, tid); cp_commit();
    g1_load_stage(sb + STAGE_BYTES, 32, bm, nt, Ahi, Alo, Wh, Wl, tid); cp_commit();

    const int arow = lane & 15;
    const int acol = (lane >> 4) * 16;
    const int brow = (lane & 7) + ((lane >> 4) << 3);
    const int bcol = ((lane >> 3) & 1) * 16;

    int s_it = 0, s_nx = 2;   // stage of current iter; stage to load next (it+2)%3
    for (int it = 0; it < NITER; ++it) {
        cp_wait<1>();
        __syncthreads();     // single barrier: load target was consumed at it-1
        if (it + 2 < NITER) {
            g1_load_stage(sb + s_nx * STAGE_BYTES, (it + 2) * 32,
                          bm, nt, Ahi, Alo, Wh, Wl, tid);
        }
        cp_commit();

        uint32_t SB = sb + s_it * STAGE_BYTES;
        s_it = (s_it == 2) ? 0 : s_it + 1;
        s_nx = (s_nx == 2) ? 0 : s_nx + 1;
#pragma unroll
        for (int ks = 0; ks < 2; ks++) {
            uint32_t rb = SB + B_OFF + (warp_n * 16 + brow) * ROWB + ks * 32 + bcol;
            uint32_t bgh[4], bgl[4], buh[4], bul[4];
            ldsm_x4(bgh, rb);
            ldsm_x4(bgl, rb + LO_OFF);
            ldsm_x4(buh, rb + 64 * ROWB);
            ldsm_x4(bul, rb + 64 * ROWB + LO_OFF);

            uint32_t af[4][4];
#pragma unroll
            for (int mi = 0; mi < 4; mi++) {
                uint32_t ra = SB + (warp_m * 64 + mi * 16 + arow) * ROWB + ks * 32 + acol;
                ldsm_x4(af[mi], ra);
            }
            // pass 1: hi * B_hi
#pragma unroll
            for (int mi = 0; mi < 4; mi++)
#pragma unroll
                for (int ni = 0; ni < 2; ni++) {
                    mma16816(accg[mi][ni], af[mi], bgh[ni*2], bgh[ni*2+1]);
                    mma16816(accu[mi][ni], af[mi], buh[ni*2], buh[ni*2+1]);
                }
            // pass 2: hi * B_lo
#pragma unroll
            for (int mi = 0; mi < 4; mi++)
#pragma unroll
                for (int ni = 0; ni < 2; ni++) {
                    mma16816(accg[mi][ni], af[mi], bgl[ni*2], bgl[ni*2+1]);
                    mma16816(accu[mi][ni], af[mi], bul[ni*2], bul[ni*2+1]);
                }
            // reload A lo into same regs
#pragma unroll
            for (int mi = 0; mi < 4; mi++) {
                uint32_t ra = SB + (warp_m * 64 + mi * 16 + arow) * ROWB + ks * 32 + acol;
                ldsm_x4(af[mi], ra + LO_OFF);
            }
            // pass 3: lo * B_hi
#pragma unroll
            for (int mi = 0; mi < 4; mi++)
#pragma unroll
                for (int ni = 0; ni < 2; ni++) {
                    mma16816(accg[mi][ni], af[mi], bgh[ni*2], bgh[ni*2+1]);
                    mma16816(accu[mi][ni], af[mi], buh[ni*2], buh[ni*2+1]);
                }
        }
    }

    // epilogue: silu(gate)*up, split, store packed pairs
    const int g = lane >> 2, t = lane & 3;
#pragma unroll
    for (int mi = 0; mi < 4; mi++)
#pragma unroll
        for (int ni = 0; ni < 2; ni++) {
            int col = nt * 64 + warp_n * 16 + ni * 8 + t * 2;
            int row0 = bm + warp_m * 64 + mi * 16 + g;
#pragma unroll
            for (int h = 0; h < 2; h++) {
                int row = row0 + h * 8;
                float g0 = accg[mi][ni][h*2],   g1 = accg[mi][ni][h*2+1];
                float u0 = accu[mi][ni][h*2],   u1 = accu[mi][ni][h*2+1];
                float x0 = u0 * g0 / (1.0f + __expf(-g0));
                float x1 = u1 * g1 / (1.0f + __expf(-g1));
                bf16 h0, l0, h1, l1;
                split1(x0, h0, l0); split1(x1, h1, l1);
                size_t o = (size_t)row * I_DIM + col;
                *reinterpret_cast<uint32_t*>(Xhi + o) = pk2(h0, h1);
                *reinterpret_cast<uint32_t*>(Xlo + o) = pk2(l0, l1);
            }
        }
}

// ============================================================================
// GEMM2: X[T,I] x Wd^T[H,I] -> out[T,H] fp32
// CTA: 256 threads, 8 warps (2m x 4n). Tile 128 tokens x 128 H-cols.
// Warp tile: 64(M) x 32(N).
// ============================================================================
__device__ __forceinline__ void g2_load_stage(
    uint32_t SB, int k0, int bm, int bn,
    const bf16* __restrict__ Xh, const bf16* __restrict__ Xl,
    const bf16* __restrict__ Dh, const bf16* __restrict__ Dl, int tid)
{
#pragma unroll
    for (int c = tid; c < 512; c += 256) {
        int row = c >> 2, kc = c & 3;
        uint32_t d = SB + row * ROWB + kc * 16;
        size_t gof = (size_t)(bm + row) * I_DIM + k0 + kc * 8;
        cp16(d,          Xh + gof);
        cp16(d + LO_OFF, Xl + gof);
    }
#pragma unroll
    for (int c = tid; c < 512; c += 256) {
        int row = c >> 2, kc = c & 3;
        uint32_t d = SB + B_OFF + row * ROWB + kc * 16;
        size_t gof = (size_t)(bn + row) * I_DIM + k0 + kc * 8;
        cp16(d,          Dh + gof);
        cp16(d + LO_OFF, Dl + gof);
    }
}

__global__ __launch_bounds__(256, 2)
void gemm2_k(const bf16* __restrict__ Xh, const bf16* __restrict__ Xl,
             const bf16* __restrict__ Dh, const bf16* __restrict__ Dl,
             float* __restrict__ out)
{
    extern __shared__ char smem[];
    const uint32_t sb = smem_u32(smem);
    const int tid = threadIdx.x, wid = tid >> 5, lane = tid & 31;
    const int warp_m = wid & 1, warp_n = wid >> 1;
    const int bn = blockIdx.x * 128;
    const int bm = blockIdx.y * 128;
    const int NITER = I_DIM / 32;               // 24

    float acc[4][4][4];
#pragma unroll
    for (int mi = 0; mi < 4; mi++)
#pragma unroll
        for (int ni = 0; ni < 4; ni++)
#pragma unroll
            for (int v = 0; v < 4; v++) acc[mi][ni][v] = 0.f;

    g2_load_stage(sb, 0, bm, bn, Xh, Xl, Dh, Dl, tid); cp_commit();
    g2_load_stage(sb + STAGE_BYTES, 32, bm, bn, Xh, Xl, Dh, Dl, tid); cp_commit();

    const int arow = lane & 15;
    const int acol = (lane >> 4) * 16;
    const int brow = (lane & 7) + ((lane >> 4) << 3);
    const int bcol = ((lane >> 3) & 1) * 16;

    int s_it = 0, s_nx = 2;
    for (int it = 0; it < NITER; ++it) {
        cp_wait<1>();
        __syncthreads();
        if (it + 2 < NITER) {
            g2_load_stage(sb + s_nx * STAGE_BYTES, (it + 2) * 32,
                          bm, bn, Xh, Xl, Dh, Dl, tid);
        }
        cp_commit();

        uint32_t SB = sb + s_it * STAGE_BYTES;
        s_it = (s_it == 2) ? 0 : s_it + 1;
        s_nx = (s_nx == 2) ? 0 : s_nx + 1;
#pragma unroll
        for (int ks = 0; ks < 2; ks++) {
            uint32_t bh[8], bl[8];
#pragma unroll
            for (int bq = 0; bq < 2; bq++) {
                uint32_t rb = SB + B_OFF + (warp_n * 32 + bq * 16 + brow) * ROWB + ks * 32 + bcol;
                ldsm_x4(&bh[bq*4], rb);
                ldsm_x4(&bl[bq*4], rb + LO_OFF);
            }
            uint32_t af[4][4];
#pragma unroll
            for (int mi = 0; mi < 4; mi++) {
                uint32_t ra = SB + (warp_m * 64 + mi * 16 + arow) * ROWB + ks * 32 + acol;
                ldsm_x4(af[mi], ra);
            }
            // pass 1: hi * B_hi
#pragma unroll
            for (int mi = 0; mi < 4; mi++)
#pragma unroll
                for (int ni = 0; ni < 4; ni++)
                    mma16816(acc[mi][ni], af[mi], bh[ni*2], bh[ni*2+1]);
            // pass 2: hi * B_lo
#pragma unroll
            for (int mi = 0; mi < 4; mi++)
#pragma unroll
                for (int ni = 0; ni < 4; ni++)
                    mma16816(acc[mi][ni], af[mi], bl[ni*2], bl[ni*2+1]);
            // reload A lo
#pragma unroll
            for (int mi = 0; mi < 4; mi++) {
                uint32_t ra = SB + (warp_m * 64 + mi * 16 + arow) * ROWB + ks * 32 + acol;
                ldsm_x4(af[mi], ra + LO_OFF);
            }
            // pass 3: lo * B_hi
#pragma unroll
            for (int mi = 0; mi < 4; mi++)
#pragma unroll
                for (int ni = 0; ni < 4; ni++)
                    mma16816(acc[mi][ni], af[mi], bh[ni*2], bh[ni*2+1]);
        }
    }

    const int g = lane >> 2, t = lane & 3;
#pragma unroll
    for (int mi = 0; mi < 4; mi++)
#pragma unroll
        for (int ni = 0; ni < 4; ni++) {
            int col = bn + warp_n * 32 + ni * 8 + t * 2;
            int row0 = bm + warp_m * 64 + mi * 16 + g;
            float2 v0 = make_float2(acc[mi][ni][0], acc[mi][ni][1]);
            float2 v1 = make_float2(acc[mi][ni][2], acc[mi][ni][3]);
            *reinterpret_cast<float2*>(out + (size_t)row0 * H_DIM + col) = v0;
            *reinterpret_cast<float2*>(out + (size_t)(row0 + 8) * H_DIM + col) = v1;
        }
}

// ---------------- prep kernels ----------------------------------------------
__global__ void split_hidden_k(const float* __restrict__ in,
                               bf16* __restrict__ hi, bf16* __restrict__ lo)
{
    size_t i = (size_t)blockIdx.x * blockDim.x + threadIdx.x;
    float4 v = reinterpret_cast<const float4*>(in)[i];
    bf16 h0, l0, h1, l1, h2, l2, h3, l3;
    split1(v.x, h0, l0); split1(v.y, h1, l1);
    split1(v.z, h2, l2); split1(v.w, h3, l3);
    uint2 ph; ph.x = pk2(h0, h1); ph.y = pk2(h2, h3);
    uint2 pl; pl.x = pk2(l0, l1); pl.y = pk2(l2, l3);
    reinterpret_cast<uint2*>(hi)[i] = ph;
    reinterpret_cast<uint2*>(lo)[i] = pl;
}

__global__ void transpose_split_k(const float* __restrict__ in,
                                  bf16* __restrict__ ohi, bf16* __restrict__ olo,
                                  int R, int C)
{
    __shared__ float t[32][33];
    int bx = blockIdx.x * 32, by = blockIdx.y * 32;
    int tx = threadIdx.x, ty = threadIdx.y;
#pragma unroll
    for (int j = 0; j < 32; j += 8)
        t[ty + j][tx] = in[(size_t)(by + ty + j) * C + bx + tx];
    __syncthreads();
#pragma unroll
    for (int j = 0; j < 32; j += 8) {
        float a = t[tx][ty + j];
        bf16 h, l; split1(a, h, l);
        size_t o = (size_t)(bx + ty + j) * R + by + tx;
        ohi[o] = h; olo[o] = l;
    }
}

// ---------------- host ------------------------------------------------------
extern "C" void kernel_launch(void* const* d_in, const int* in_sizes, int n_in,
                              void* d_out, int out_size)
{
    const float* hidden = (const float*)d_in[0];   // [T, H]
    const float* wgu    = (const float*)d_in[1];   // [H, 2I]
    const float* wd     = (const float*)d_in[2];   // [I, H]
    float* out = (float*)d_out;                    // [T, H]

    bf16 *Ahi, *Alo, *Wh, *Wl, *Dh, *Dl, *Xh, *Xl;
    cudaGetSymbolAddress((void**)&Ahi, g_Ahi);
    cudaGetSymbolAddress((void**)&Alo, g_Alo);
    cudaGetSymbolAddress((void**)&Wh,  g_Wgu_hi);
    cudaGetSymbolAddress((void**)&Wl,  g_Wgu_lo);
    cudaGetSymbolAddress((void**)&Dh,  g_Wd_hi);
    cudaGetSymbolAddress((void**)&Dl,  g_Wd_lo);
    cudaGetSymbolAddress((void**)&Xh,  g_Xhi);
    cudaGetSymbolAddress((void**)&Xl,  g_Xlo);

    cudaFuncSetAttribute(gemm1_k, cudaFuncAttributeMaxDynamicSharedMemorySize, SMEM_BYTES);
    cudaFuncSetAttribute(gemm2_k, cudaFuncAttributeMaxDynamicSharedMemorySize, SMEM_BYTES);

    split_hidden_k<<<(int)(((size_t)T_TOK * H_DIM / 4) / 256), 256>>>(hidden, Ahi, Alo);
    transpose_split_k<<<dim3(2 * I_DIM / 32, H_DIM / 32), dim3(32, 8)>>>(wgu, Wh, Wl, H_DIM, 2 * I_DIM);
    transpose_split_k<<<dim3(H_DIM / 32, I_DIM / 32), dim3(32, 8)>>>(wd, Dh, Dl, I_DIM, H_DIM);

    gemm1_k<<<dim3(I_DIM / 64, T_TOK / 128), 256, SMEM_BYTES>>>(Ahi, Alo, Wh, Wl, Xh, Xl);
    gemm2_k<<<dim3(H_DIM / 128, T_TOK / 128), 256, SMEM_BYTES>>>(Xh, Xl, Dh, Dl, out);
}

// round 10
// speedup vs baseline: 2.6157x; 2.3993x over previous
#include <cuda_runtime.h>
#include <cuda_fp16.h>
#include <cstdint>

#define T_TOK 32768
#define H_DIM 2048
#define I_DIM 768

// ---------------- static device scratch (fp16) ------------------------------
__device__ __half g_Ah[(size_t)T_TOK * H_DIM];          // hidden   [T,H]
__device__ __half g_Wgu[(size_t)2 * I_DIM * H_DIM];     // w_gate_up^T [2I,H]
__device__ __half g_Wd[(size_t)H_DIM * I_DIM];          // w_down^T    [H,I]
__device__ __half g_X[(size_t)T_TOK * I_DIM];           // silu(g)*u   [T,I]

// ---------------- helpers ----------------------------------------------------
__device__ __forceinline__ uint32_t smem_u32(const void* p) {
    return (uint32_t)__cvta_generic_to_shared(p);
}
__device__ __forceinline__ void cp16(uint32_t dst, const void* src) {
    asm volatile("cp.async.cg.shared.global [%0], [%1], 16;" :: "r"(dst), "l"(src));
}
__device__ __forceinline__ void cp_commit() {
    asm volatile("cp.async.commit_group;" ::: "memory");
}
template <int N>
__device__ __forceinline__ void cp_wait() {
    asm volatile("cp.async.wait_group %0;" :: "n"(N) : "memory");
}
__device__ __forceinline__ void ldsm_x4(uint32_t* r, uint32_t addr) {
    asm volatile("ldmatrix.sync.aligned.m8n8.x4.shared.b16 {%0,%1,%2,%3}, [%4];"
                 : "=r"(r[0]), "=r"(r[1]), "=r"(r[2]), "=r"(r[3]) : "r"(addr));
}
__device__ __forceinline__ void mma16816(float* d, const uint32_t* a,
                                         uint32_t b0, uint32_t b1) {
    asm volatile(
        "mma.sync.aligned.m16n8k16.row.col.f32.f16.f16.f32 "
        "{%0,%1,%2,%3}, {%4,%5,%6,%7}, {%8,%9}, {%0,%1,%2,%3};"
        : "+f"(d[0]), "+f"(d[1]), "+f"(d[2]), "+f"(d[3])
        : "r"(a[0]), "r"(a[1]), "r"(a[2]), "r"(a[3]), "r"(b0), "r"(b1));
}
__device__ __forceinline__ uint32_t pk2h(float a, float b) {
    __half2 t = __floats2half2_rn(a, b);
    return *reinterpret_cast<uint32_t*>(&t);
}

// SMEM stage: rows of 32 fp16 = 64B data + 16B pad -> stride 80B (20 words).
// 8-row ldmatrix bank starts (r*20)%32 = {0,20,8,28,16,4,24,12}: conflict-free.
//   A tile (128 rows) @0, B tile (128 rows) @10240
#define ROWB        80
#define B_OFF       10240
#define STAGE_BYTES 20480
#define NSTAGE      5
#define PFD         4          // prefetch distance (>= NSTAGE-1 for single barrier)
#define SMEM_BYTES  (NSTAGE * STAGE_BYTES)

// ============================================================================
// GEMM1: hidden[T,H] x Wgu^T[2I,H] -> silu(gate)*up -> X[T,I] fp16
// CTA: 256 thr, 8 warps (2m x 4n). Tile 128 tokens x 64 I-cols (gate+up).
// Warp tile: 64(M) x 16(N) for both gate and up accumulators.
// ============================================================================
__device__ __forceinline__ void g1_load_stage(
    uint32_t SB, int k0, int bm, int nt,
    const __half* __restrict__ A, const __half* __restrict__ W, int tid)
{
#pragma unroll
    for (int c = tid; c < 512; c += 256) {            // A: 128 rows x 4 x 16B
        int row = c >> 2, kc = c & 3;
        cp16(SB + row * ROWB + kc * 16,
             A + (size_t)(bm + row) * H_DIM + k0 + kc * 8);
    }
#pragma unroll
    for (int c = tid; c < 512; c += 256) {            // B: 64 gate + 64 up rows
        int row = c >> 2, kc = c & 3;
        int gr = (row < 64) ? (nt * 64 + row) : (I_DIM + nt * 64 + row - 64);
        cp16(SB + B_OFF + row * ROWB + kc * 16,
             W + (size_t)gr * H_DIM + k0 + kc * 8);
    }
}

__global__ __launch_bounds__(256, 2)
void gemm1_k(const __half* __restrict__ A, const __half* __restrict__ W,
             __half* __restrict__ X)
{
    extern __shared__ char smem[];
    const uint32_t sb = smem_u32(smem);
    const int tid = threadIdx.x, wid = tid >> 5, lane = tid & 31;
    const int warp_m = wid & 1, warp_n = wid >> 1;
    const int nt = blockIdx.x;                  // 0..11
    const int bm = blockIdx.y * 128;
    const int NITER = H_DIM / 32;               // 64

    float accg[4][2][4], accu[4][2][4];
#pragma unroll
    for (int mi = 0; mi < 4; mi++)
#pragma unroll
        for (int ni = 0; ni < 2; ni++)
#pragma unroll
            for (int v = 0; v < 4; v++) { accg[mi][ni][v] = 0.f; accu[mi][ni][v] = 0.f; }

    // prologue: fill PFD stages
#pragma unroll
    for (int p = 0; p < PFD; p++) {
        g1_load_stage(sb + p * STAGE_BYTES, p * 32, bm, nt, A, W, tid);
        cp_commit();
    }

    const int arow = lane & 15;
    const int acol = (lane >> 4) * 16;
    const int brow = (lane & 7) + ((lane >> 4) << 3);
    const int bcol = ((lane >> 3) & 1) * 16;

    int s_it = 0, s_nx = PFD % NSTAGE;
    for (int it = 0; it < NITER; ++it) {
        cp_wait<PFD - 1>();
        __syncthreads();          // load target consumed >=1 iter ago (PFD>=NSTAGE-1)
        if (it + PFD < NITER) {
            g1_load_stage(sb + s_nx * STAGE_BYTES, (it + PFD) * 32, bm, nt, A, W, tid);
        }
        cp_commit();

        uint32_t SB = sb + s_it * STAGE_BYTES;
        s_it = (s_it == NSTAGE - 1) ? 0 : s_it + 1;
        s_nx = (s_nx == NSTAGE - 1) ? 0 : s_nx + 1;
#pragma unroll
        for (int ks = 0; ks < 2; ks++) {
            uint32_t rb = SB + B_OFF + (warp_n * 16 + brow) * ROWB + ks * 32 + bcol;
            uint32_t bg[4], bu[4];
            ldsm_x4(bg, rb);
            ldsm_x4(bu, rb + 64 * ROWB);

            uint32_t af[4][4];
#pragma unroll
            for (int mi = 0; mi < 4; mi++) {
                uint32_t ra = SB + (warp_m * 64 + mi * 16 + arow) * ROWB + ks * 32 + acol;
                ldsm_x4(af[mi], ra);
            }
#pragma unroll
            for (int mi = 0; mi < 4; mi++)
#pragma unroll
                for (int ni = 0; ni < 2; ni++) {
                    mma16816(accg[mi][ni], af[mi], bg[ni*2], bg[ni*2+1]);
                    mma16816(accu[mi][ni], af[mi], bu[ni*2], bu[ni*2+1]);
                }
        }
    }

    // epilogue: silu(gate)*up -> fp16 X
    const int g = lane >> 2, t = lane & 3;
#pragma unroll
    for (int mi = 0; mi < 4; mi++)
#pragma unroll
        for (int ni = 0; ni < 2; ni++) {
            int col = nt * 64 + warp_n * 16 + ni * 8 + t * 2;
            int row0 = bm + warp_m * 64 + mi * 16 + g;
#pragma unroll
            for (int h = 0; h < 2; h++) {
                int row = row0 + h * 8;
                float g0 = accg[mi][ni][h*2],   g1 = accg[mi][ni][h*2+1];
                float u0 = accu[mi][ni][h*2],   u1 = accu[mi][ni][h*2+1];
                float x0 = u0 * g0 / (1.0f + __expf(-g0));
                float x1 = u1 * g1 / (1.0f + __expf(-g1));
                *reinterpret_cast<uint32_t*>(X + (size_t)row * I_DIM + col) = pk2h(x0, x1);
            }
        }
}

// ============================================================================
// GEMM2: X[T,I] x Wd^T[H,I] -> out[T,H] fp32
// CTA: 256 thr, 8 warps (2m x 4n). Tile 128 tokens x 128 H-cols.
// Warp tile: 64(M) x 32(N).
// ============================================================================
__device__ __forceinline__ void g2_load_stage(
    uint32_t SB, int k0, int bm, int bn,
    const __half* __restrict__ X, const __half* __restrict__ D, int tid)
{
#pragma unroll
    for (int c = tid; c < 512; c += 256) {
        int row = c >> 2, kc = c & 3;
        cp16(SB + row * ROWB + kc * 16,
             X + (size_t)(bm + row) * I_DIM + k0 + kc * 8);
    }
#pragma unroll
    for (int c = tid; c < 512; c += 256) {
        int row = c >> 2, kc = c & 3;
        cp16(SB + B_OFF + row * ROWB + kc * 16,
             D + (size_t)(bn + row) * I_DIM + k0 + kc * 8);
    }
}

__global__ __launch_bounds__(256, 2)
void gemm2_k(const __half* __restrict__ X, const __half* __restrict__ D,
             float* __restrict__ out)
{
    extern __shared__ char smem[];
    const uint32_t sb = smem_u32(smem);
    const int tid = threadIdx.x, wid = tid >> 5, lane = tid & 31;
    const int warp_m = wid & 1, warp_n = wid >> 1;
    const int bn = blockIdx.x * 128;
    const int bm = blockIdx.y * 128;
    const int NITER = I_DIM / 32;               // 24

    float acc[4][4][4];
#pragma unroll
    for (int mi = 0; mi < 4; mi++)
#pragma unroll
        for (int ni = 0; ni < 4; ni++)
#pragma unroll
            for (int v = 0; v < 4; v++) acc[mi][ni][v] = 0.f;

#pragma unroll
    for (int p = 0; p < PFD; p++) {
        g2_load_stage(sb + p * STAGE_BYTES, p * 32, bm, bn, X, D, tid);
        cp_commit();
    }

    const int arow = lane & 15;
    const int acol = (lane >> 4) * 16;
    const int brow = (lane & 7) + ((lane >> 4) << 3);
    const int bcol = ((lane >> 3) & 1) * 16;

    int s_it = 0, s_nx = PFD % NSTAGE;
    for (int it = 0; it < NITER; ++it) {
        cp_wait<PFD - 1>();
        __syncthreads();
        if (it + PFD < NITER) {
            g2_load_stage(sb + s_nx * STAGE_BYTES, (it + PFD) * 32, bm, bn, X, D, tid);
        }
        cp_commit();

        uint32_t SB = sb + s_it * STAGE_BYTES;
        s_it = (s_it == NSTAGE - 1) ? 0 : s_it + 1;
        s_nx = (s_nx == NSTAGE - 1) ? 0 : s_nx + 1;
#pragma unroll
        for (int ks = 0; ks < 2; ks++) {
            uint32_t bf[8];
#pragma unroll
            for (int bq = 0; bq < 2; bq++) {
                uint32_t rb = SB + B_OFF + (warp_n * 32 + bq * 16 + brow) * ROWB + ks * 32 + bcol;
                ldsm_x4(&bf[bq*4], rb);
            }
            uint32_t af[4][4];
#pragma unroll
            for (int mi = 0; mi < 4; mi++) {
                uint32_t ra = SB + (warp_m * 64 + mi * 16 + arow) * ROWB + ks * 32 + acol;
                ldsm_x4(af[mi], ra);
            }
#pragma unroll
            for (int mi = 0; mi < 4; mi++)
#pragma unroll
                for (int ni = 0; ni < 4; ni++)
                    mma16816(acc[mi][ni], af[mi], bf[ni*2], bf[ni*2+1]);
        }
    }

    const int g = lane >> 2, t = lane & 3;
#pragma unroll
    for (int mi = 0; mi < 4; mi++)
#pragma unroll
        for (int ni = 0; ni < 4; ni++) {
            int col = bn + warp_n * 32 + ni * 8 + t * 2;
            int row0 = bm + warp_m * 64 + mi * 16 + g;
            float2 v0 = make_float2(acc[mi][ni][0], acc[mi][ni][1]);
            float2 v1 = make_float2(acc[mi][ni][2], acc[mi][ni][3]);
            *reinterpret_cast<float2*>(out + (size_t)row0 * H_DIM + col) = v0;
            *reinterpret_cast<float2*>(out + (size_t)(row0 + 8) * H_DIM + col) = v1;
        }
}

// ---------------- prep kernels ----------------------------------------------
__global__ void conv_hidden_k(const float* __restrict__ in, __half* __restrict__ o)
{
    size_t i = (size_t)blockIdx.x * blockDim.x + threadIdx.x;
    float4 v = reinterpret_cast<const float4*>(in)[i];
    uint2 p;
    p.x = pk2h(v.x, v.y);
    p.y = pk2h(v.z, v.w);
    reinterpret_cast<uint2*>(o)[i] = p;
}

__global__ void transpose_conv_k(const float* __restrict__ in,
                                 __half* __restrict__ o, int R, int C)
{
    __shared__ float t[32][33];
    int bx = blockIdx.x * 32, by = blockIdx.y * 32;
    int tx = threadIdx.x, ty = threadIdx.y;
#pragma unroll
    for (int j = 0; j < 32; j += 8)
        t[ty + j][tx] = in[(size_t)(by + ty + j) * C + bx + tx];
    __syncthreads();
#pragma unroll
    for (int j = 0; j < 32; j += 8) {
        float a = t[tx][ty + j];
        o[(size_t)(bx + ty + j) * R + by + tx] = __float2half_rn(a);
    }
}

// ---------------- host ------------------------------------------------------
extern "C" void kernel_launch(void* const* d_in, const int* in_sizes, int n_in,
                              void* d_out, int out_size)
{
    const float* hidden = (const float*)d_in[0];   // [T, H]
    const float* wgu    = (const float*)d_in[1];   // [H, 2I]
    const float* wd     = (const float*)d_in[2];   // [I, H]
    float* out = (float*)d_out;                    // [T, H]

    __half *Ah, *W, *D, *X;
    cudaGetSymbolAddress((void**)&Ah, g_Ah);
    cudaGetSymbolAddress((void**)&W,  g_Wgu);
    cudaGetSymbolAddress((void**)&D,  g_Wd);
    cudaGetSymbolAddress((void**)&X,  g_X);

    cudaFuncSetAttribute(gemm1_k, cudaFuncAttributeMaxDynamicSharedMemorySize, SMEM_BYTES);
    cudaFuncSetAttribute(gemm2_k, cudaFuncAttributeMaxDynamicSharedMemorySize, SMEM_BYTES);

    conv_hidden_k<<<(int)(((size_t)T_TOK * H_DIM / 4) / 256), 256>>>(hidden, Ah);
    transpose_conv_k<<<dim3(2 * I_DIM / 32, H_DIM / 32), dim3(32, 8)>>>(wgu, W, H_DIM, 2 * I_DIM);
    transpose_conv_k<<<dim3(H_DIM / 32, I_DIM / 32), dim3(32, 8)>>>(wd, D, I_DIM, H_DIM);

    gemm1_k<<<dim3(I_DIM / 64, T_TOK / 128), 256, SMEM_BYTES>>>(Ah, W, X);
    gemm2_k<<<dim3(H_DIM / 128, T_TOK / 128), 256, SMEM_BYTES>>>(X, D, out);
}

// round 11
// speedup vs baseline: 2.9839x; 1.1407x over previous
#include <cuda_runtime.h>
#include <cuda_fp16.h>
#include <cstdint>

#define T_TOK 32768
#define H_DIM 2048
#define I_DIM 768

// ---------------- static device scratch (fp16) ------------------------------
__device__ __half g_Ah[(size_t)T_TOK * H_DIM];          // hidden   [T,H]
__device__ __half g_Wgu[(size_t)2 * I_DIM * H_DIM];     // w_gate_up^T [2I,H]
__device__ __half g_Wd[(size_t)H_DIM * I_DIM];          // w_down^T    [H,I]
__device__ __half g_X[(size_t)T_TOK * I_DIM];           // silu(g)*u   [T,I]

// ---------------- helpers ----------------------------------------------------
__device__ __forceinline__ uint32_t smem_u32(const void* p) {
    return (uint32_t)__cvta_generic_to_shared(p);
}
__device__ __forceinline__ void cp16(uint32_t dst, const void* src) {
    asm volatile("cp.async.cg.shared.global [%0], [%1], 16;" :: "r"(dst), "l"(src));
}
__device__ __forceinline__ void cp_commit() {
    asm volatile("cp.async.commit_group;" ::: "memory");
}
template <int N>
__device__ __forceinline__ void cp_wait() {
    asm volatile("cp.async.wait_group %0;" :: "n"(N) : "memory");
}
__device__ __forceinline__ void ldsm_x4(uint32_t* r, uint32_t addr) {
    asm volatile("ldmatrix.sync.aligned.m8n8.x4.shared.b16 {%0,%1,%2,%3}, [%4];"
                 : "=r"(r[0]), "=r"(r[1]), "=r"(r[2]), "=r"(r[3]) : "r"(addr));
}
__device__ __forceinline__ void mma16816(float* d, const uint32_t* a,
                                         uint32_t b0, uint32_t b1) {
    asm volatile(
        "mma.sync.aligned.m16n8k16.row.col.f32.f16.f16.f32 "
        "{%0,%1,%2,%3}, {%4,%5,%6,%7}, {%8,%9}, {%0,%1,%2,%3};"
        : "+f"(d[0]), "+f"(d[1]), "+f"(d[2]), "+f"(d[3])
        : "r"(a[0]), "r"(a[1]), "r"(a[2]), "r"(a[3]), "r"(b0), "r"(b1));
}
__device__ __forceinline__ uint32_t pk2h(float a, float b) {
    __half2 t = __floats2half2_rn(a, b);
    return *reinterpret_cast<uint32_t*>(&t);
}

// SMEM stage: rows of 32 fp16 = 64B data + 16B pad -> stride 80B (20 words).
// 8-row ldmatrix bank starts (r*20)%32 = {0,20,8,28,16,4,24,12}: conflict-free.
//   A tile (128 rows) @0, B tile (128 rows) @10240
#define ROWB        80
#define B_OFF       10240
#define STAGE_BYTES 20480
#define NSTAGE      5
#define PFD         4          // prefetch distance (>= NSTAGE-1 for single barrier)
#define SMEM_BYTES  (NSTAGE * STAGE_BYTES)

// ============================================================================
// GEMM1: hidden[T,H] x Wgu^T[2I,H] -> silu(gate)*up -> X[T,I] fp16
// CTA: 128 thr, 4 warps (2m x 2n). CTA tile 128 tokens x 64 I-cols.
// B tile: per 64-row warp_n chunk = [32 gate rows | 32 up rows] (same I-cols),
// so gate/up pairs live in the same warp: acc[ni] (gate) vs acc[ni+4] (up).
// Warp tile: 64(M) x 64(N).
// ============================================================================
__device__ __forceinline__ void g1_load_stage(
    uint32_t SB, int k0, int bm, int nt,
    const __half* __restrict__ A, const __half* __restrict__ W, int tid)
{
#pragma unroll
    for (int c = tid; c < 512; c += 128) {            // A: 128 rows x 4 x 16B
        int row = c >> 2, kc = c & 3;
        cp16(SB + row * ROWB + kc * 16,
             A + (size_t)(bm + row) * H_DIM + k0 + kc * 8);
    }
#pragma unroll
    for (int c = tid; c < 512; c += 128) {            // B: interleaved gate/up
        int row = c >> 2, kc = c & 3;
        int wn = row >> 6, r = row & 63;
        int gr = (r < 32) ? (nt * 64 + wn * 32 + r)
                          : (I_DIM + nt * 64 + wn * 32 + r - 32);
        cp16(SB + B_OFF + row * ROWB + kc * 16,
             W + (size_t)gr * H_DIM + k0 + kc * 8);
    }
}

__global__ __launch_bounds__(128, 2)
void gemm1_k(const __half* __restrict__ A, const __half* __restrict__ W,
             __half* __restrict__ X)
{
    extern __shared__ char smem[];
    const uint32_t sb = smem_u32(smem);
    const int tid = threadIdx.x, wid = tid >> 5, lane = tid & 31;
    const int warp_m = wid & 1, warp_n = wid >> 1;
    const int nt = blockIdx.x;                  // 0..11 (64 I-cols each)
    const int bm = blockIdx.y * 128;
    const int NITER = H_DIM / 32;               // 64

    float acc[4][8][4];                         // ni 0..3 gate, 4..7 up
#pragma unroll
    for (int mi = 0; mi < 4; mi++)
#pragma unroll
        for (int ni = 0; ni < 8; ni++)
#pragma unroll
            for (int v = 0; v < 4; v++) acc[mi][ni][v] = 0.f;

#pragma unroll
    for (int p = 0; p < PFD; p++) {
        g1_load_stage(sb + p * STAGE_BYTES, p * 32, bm, nt, A, W, tid);
        cp_commit();
    }

    const int arow = lane & 15;
    const int acol = (lane >> 4) * 16;
    const int brow = (lane & 7) + ((lane >> 4) << 3);
    const int bcol = ((lane >> 3) & 1) * 16;

    int s_it = 0, s_nx = PFD % NSTAGE;
    for (int it = 0; it < NITER; ++it) {
        cp_wait<PFD - 1>();
        __syncthreads();
        if (it + PFD < NITER) {
            g1_load_stage(sb + s_nx * STAGE_BYTES, (it + PFD) * 32, bm, nt, A, W, tid);
        }
        cp_commit();

        uint32_t SB = sb + s_it * STAGE_BYTES;
        s_it = (s_it == NSTAGE - 1) ? 0 : s_it + 1;
        s_nx = (s_nx == NSTAGE - 1) ? 0 : s_nx + 1;
#pragma unroll
        for (int ks = 0; ks < 2; ks++) {
            uint32_t bf[16];
#pragma unroll
            for (int bq = 0; bq < 4; bq++) {
                uint32_t rb = SB + B_OFF + (warp_n * 64 + bq * 16 + brow) * ROWB
                            + ks * 32 + bcol;
                ldsm_x4(&bf[bq * 4], rb);
            }
            uint32_t af[4][4];
#pragma unroll
            for (int mi = 0; mi < 4; mi++) {
                uint32_t ra = SB + (warp_m * 64 + mi * 16 + arow) * ROWB + ks * 32 + acol;
                ldsm_x4(af[mi], ra);
            }
#pragma unroll
            for (int mi = 0; mi < 4; mi++)
#pragma unroll
                for (int ni = 0; ni < 8; ni++)
                    mma16816(acc[mi][ni], af[mi], bf[ni * 2], bf[ni * 2 + 1]);
        }
    }

    // epilogue: silu(gate)*up -> fp16 X (gate=acc[ni], up=acc[ni+4])
    const int g = lane >> 2, t = lane & 3;
#pragma unroll
    for (int mi = 0; mi < 4; mi++)
#pragma unroll
        for (int ni = 0; ni < 4; ni++) {
            int col = nt * 64 + warp_n * 32 + ni * 8 + t * 2;
            int row0 = bm + warp_m * 64 + mi * 16 + g;
#pragma unroll
            for (int h = 0; h < 2; h++) {
                int row = row0 + h * 8;
                float g0 = acc[mi][ni][h*2],     g1 = acc[mi][ni][h*2+1];
                float u0 = acc[mi][ni+4][h*2],   u1 = acc[mi][ni+4][h*2+1];
                float x0 = u0 * g0 / (1.0f + __expf(-g0));
                float x1 = u1 * g1 / (1.0f + __expf(-g1));
                *reinterpret_cast<uint32_t*>(X + (size_t)row * I_DIM + col) = pk2h(x0, x1);
            }
        }
}

// ============================================================================
// GEMM2: X[T,I] x Wd^T[H,I] -> out[T,H] fp32
// CTA: 128 thr, 4 warps (2m x 2n). Tile 128 tokens x 128 H-cols.
// Warp tile: 64(M) x 64(N).
// ============================================================================
__device__ __forceinline__ void g2_load_stage(
    uint32_t SB, int k0, int bm, int bn,
    const __half* __restrict__ X, const __half* __restrict__ D, int tid)
{
#pragma unroll
    for (int c = tid; c < 512; c += 128) {
        int row = c >> 2, kc = c & 3;
        cp16(SB + row * ROWB + kc * 16,
             X + (size_t)(bm + row) * I_DIM + k0 + kc * 8);
    }
#pragma unroll
    for (int c = tid; c < 512; c += 128) {
        int row = c >> 2, kc = c & 3;
        cp16(SB + B_OFF + row * ROWB + kc * 16,
             D + (size_t)(bn + row) * I_DIM + k0 + kc * 8);
    }
}

__global__ __launch_bounds__(128, 2)
void gemm2_k(const __half* __restrict__ X, const __half* __restrict__ D,
             float* __restrict__ out)
{
    extern __shared__ char smem[];
    const uint32_t sb = smem_u32(smem);
    const int tid = threadIdx.x, wid = tid >> 5, lane = tid & 31;
    const int warp_m = wid & 1, warp_n = wid >> 1;
    const int bn = blockIdx.x * 128;
    const int bm = blockIdx.y * 128;
    const int NITER = I_DIM / 32;               // 24

    float acc[4][8][4];
#pragma unroll
    for (int mi = 0; mi < 4; mi++)
#pragma unroll
        for (int ni = 0; ni < 8; ni++)
#pragma unroll
            for (int v = 0; v < 4; v++) acc[mi][ni][v] = 0.f;

#pragma unroll
    for (int p = 0; p < PFD; p++) {
        g2_load_stage(sb + p * STAGE_BYTES, p * 32, bm, bn, X, D, tid);
        cp_commit();
    }

    const int arow = lane & 15;
    const int acol = (lane >> 4) * 16;
    const int brow = (lane & 7) + ((lane >> 4) << 3);
    const int bcol = ((lane >> 3) & 1) * 16;

    int s_it = 0, s_nx = PFD % NSTAGE;
    for (int it = 0; it < NITER; ++it) {
        cp_wait<PFD - 1>();
        __syncthreads();
        if (it + PFD < NITER) {
            g2_load_stage(sb + s_nx * STAGE_BYTES, (it + PFD) * 32, bm, bn, X, D, tid);
        }
        cp_commit();

        uint32_t SB = sb + s_it * STAGE_BYTES;
        s_it = (s_it == NSTAGE - 1) ? 0 : s_it + 1;
        s_nx = (s_nx == NSTAGE - 1) ? 0 : s_nx + 1;
#pragma unroll
        for (int ks = 0; ks < 2; ks++) {
            uint32_t bf[16];
#pragma unroll
            for (int bq = 0; bq < 4; bq++) {
                uint32_t rb = SB + B_OFF + (warp_n * 64 + bq * 16 + brow) * ROWB
                            + ks * 32 + bcol;
                ldsm_x4(&bf[bq * 4], rb);
            }
            uint32_t af[4][4];
#pragma unroll
            for (int mi = 0; mi < 4; mi++) {
                uint32_t ra = SB + (warp_m * 64 + mi * 16 + arow) * ROWB + ks * 32 + acol;
                ldsm_x4(af[mi], ra);
            }
#pragma unroll
            for (int mi = 0; mi < 4; mi++)
#pragma unroll
                for (int ni = 0; ni < 8; ni++)
                    mma16816(acc[mi][ni], af[mi], bf[ni * 2], bf[ni * 2 + 1]);
        }
    }

    const int g = lane >> 2, t = lane & 3;
#pragma unroll
    for (int mi = 0; mi < 4; mi++)
#pragma unroll
        for (int ni = 0; ni < 8; ni++) {
            int col = bn + warp_n * 64 + ni * 8 + t * 2;
            int row0 = bm + warp_m * 64 + mi * 16 + g;
            float2 v0 = make_float2(acc[mi][ni][0], acc[mi][ni][1]);
            float2 v1 = make_float2(acc[mi][ni][2], acc[mi][ni][3]);
            *reinterpret_cast<float2*>(out + (size_t)row0 * H_DIM + col) = v0;
            *reinterpret_cast<float2*>(out + (size_t)(row0 + 8) * H_DIM + col) = v1;
        }
}

// ---------------- prep kernels ----------------------------------------------
__global__ void conv_hidden_k(const float* __restrict__ in, __half* __restrict__ o)
{
    size_t i = (size_t)blockIdx.x * blockDim.x + threadIdx.x;
    float4 v = reinterpret_cast<const float4*>(in)[i];
    uint2 p;
    p.x = pk2h(v.x, v.y);
    p.y = pk2h(v.z, v.w);
    reinterpret_cast<uint2*>(o)[i] = p;
}

__global__ void transpose_conv_k(const float* __restrict__ in,
                                 __half* __restrict__ o, int R, int C)
{
    __shared__ float t[32][33];
    int bx = blockIdx.x * 32, by = blockIdx.y * 32;
    int tx = threadIdx.x, ty = threadIdx.y;
#pragma unroll
    for (int j = 0; j < 32; j += 8)
        t[ty + j][tx] = in[(size_t)(by + ty + j) * C + bx + tx];
    __syncthreads();
#pragma unroll
    for (int j = 0; j < 32; j += 8) {
        float a = t[tx][ty + j];
        o[(size_t)(bx + ty + j) * R + by + tx] = __float2half_rn(a);
    }
}

// ---------------- host ------------------------------------------------------
extern "C" void kernel_launch(void* const* d_in, const int* in_sizes, int n_in,
                              void* d_out, int out_size)
{
    const float* hidden = (const float*)d_in[0];   // [T, H]
    const float* wgu    = (const float*)d_in[1];   // [H, 2I]
    const float* wd     = (const float*)d_in[2];   // [I, H]
    float* out = (float*)d_out;                    // [T, H]

    __half *Ah, *W, *D, *X;
    cudaGetSymbolAddress((void**)&Ah, g_Ah);
    cudaGetSymbolAddress((void**)&W,  g_Wgu);
    cudaGetSymbolAddress((void**)&D,  g_Wd);
    cudaGetSymbolAddress((void**)&X,  g_X);

    cudaFuncSetAttribute(gemm1_k, cudaFuncAttributeMaxDynamicSharedMemorySize, SMEM_BYTES);
    cudaFuncSetAttribute(gemm2_k, cudaFuncAttributeMaxDynamicSharedMemorySize, SMEM_BYTES);

    conv_hidden_k<<<(int)(((size_t)T_TOK * H_DIM / 4) / 256), 256>>>(hidden, Ah);
    transpose_conv_k<<<dim3(2 * I_DIM / 32, H_DIM / 32), dim3(32, 8)>>>(wgu, W, H_DIM, 2 * I_DIM);
    transpose_conv_k<<<dim3(H_DIM / 32, I_DIM / 32), dim3(32, 8)>>>(wd, D, I_DIM, H_DIM);

    gemm1_k<<<dim3(I_DIM / 64, T_TOK / 128), 128, SMEM_BYTES>>>(Ah, W, X);
    gemm2_k<<<dim3(H_DIM / 128, T_TOK / 128), 128, SMEM_BYTES>>>(X, D, out);
}

// round 12
// speedup vs baseline: 2.9847x; 1.0003x over previous
#include <cuda_runtime.h>
#include <cuda_fp16.h>
#include <cstdint>

#define T_TOK 32768
#define H_DIM 2048
#define I_DIM 768

// ---------------- static device scratch (fp16) ------------------------------
__device__ __half g_Ah[(size_t)T_TOK * H_DIM];          // hidden   [T,H]
__device__ __half g_Wgu[(size_t)2 * I_DIM * H_DIM];     // w_gate_up^T [2I,H]
__device__ __half g_Wd[(size_t)H_DIM * I_DIM];          // w_down^T    [H,I]
__device__ __half g_X[(size_t)T_TOK * I_DIM];           // silu(g)*u   [T,I]

// ---------------- helpers ----------------------------------------------------
__device__ __forceinline__ uint32_t smem_u32(const void* p) {
    return (uint32_t)__cvta_generic_to_shared(p);
}
__device__ __forceinline__ void cp16(uint32_t dst, const void* src) {
    asm volatile("cp.async.cg.shared.global [%0], [%1], 16;" :: "r"(dst), "l"(src));
}
__device__ __forceinline__ void cp_commit() {
    asm volatile("cp.async.commit_group;" ::: "memory");
}
template <int N>
__device__ __forceinline__ void cp_wait() {
    asm volatile("cp.async.wait_group %0;" :: "n"(N) : "memory");
}
__device__ __forceinline__ void ldsm_x4(uint32_t* r, uint32_t addr) {
    asm volatile("ldmatrix.sync.aligned.m8n8.x4.shared.b16 {%0,%1,%2,%3}, [%4];"
                 : "=r"(r[0]), "=r"(r[1]), "=r"(r[2]), "=r"(r[3]) : "r"(addr));
}
__device__ __forceinline__ void mma16816(float* d, const uint32_t* a,
                                         uint32_t b0, uint32_t b1) {
    asm volatile(
        "mma.sync.aligned.m16n8k16.row.col.f32.f16.f16.f32 "
        "{%0,%1,%2,%3}, {%4,%5,%6,%7}, {%8,%9}, {%0,%1,%2,%3};"
        : "+f"(d[0]), "+f"(d[1]), "+f"(d[2]), "+f"(d[3])
        : "r"(a[0]), "r"(a[1]), "r"(a[2]), "r"(a[3]), "r"(b0), "r"(b1));
}
__device__ __forceinline__ uint32_t pk2h(float a, float b) {
    __half2 t = __floats2half2_rn(a, b);
    return *reinterpret_cast<uint32_t*>(&t);
}

// SMEM stage: rows of 32 fp16 = 64B data + 16B pad -> stride 80B (20 words).
// 8-row ldmatrix bank starts (r*20)%32 = {0,20,8,28,16,4,24,12}: conflict-free.
//   A tile (128 rows) @0, B tile (128 rows) @10240
#define ROWB        80
#define B_OFF       10240
#define STAGE_BYTES 20480
#define NSTAGE      5
#define PFD         4
#define SMEM_BYTES  (NSTAGE * STAGE_BYTES)

// ============================================================================
// GEMM1: hidden[T,H] x Wgu^T[2I,H] -> silu(gate)*up -> X[T,I] fp16
// CTA: 128 thr, 4 warps (2m x 2n). CTA tile 128 tokens x 64 I-cols.
// Warp tile 64x64. Whole-iteration fragment hoisting.
// ============================================================================
__device__ __forceinline__ void g1_load_stage(
    uint32_t SB, int k0, int bm, int nt,
    const __half* __restrict__ A, const __half* __restrict__ W, int tid)
{
#pragma unroll
    for (int c = tid; c < 512; c += 128) {            // A: 128 rows x 4 x 16B
        int row = c >> 2, kc = c & 3;
        cp16(SB + row * ROWB + kc * 16,
             A + (size_t)(bm + row) * H_DIM + k0 + kc * 8);
    }
#pragma unroll
    for (int c = tid; c < 512; c += 128) {            // B: interleaved gate/up
        int row = c >> 2, kc = c & 3;
        int wn = row >> 6, r = row & 63;
        int gr = (r < 32) ? (nt * 64 + wn * 32 + r)
                          : (I_DIM + nt * 64 + wn * 32 + r - 32);
        cp16(SB + B_OFF + row * ROWB + kc * 16,
             W + (size_t)gr * H_DIM + k0 + kc * 8);
    }
}

__global__ __launch_bounds__(128, 2)
void gemm1_k(const __half* __restrict__ A, const __half* __restrict__ W,
             __half* __restrict__ X)
{
    extern __shared__ char smem[];
    const uint32_t sb = smem_u32(smem);
    const int tid = threadIdx.x, wid = tid >> 5, lane = tid & 31;
    const int warp_m = wid & 1, warp_n = wid >> 1;
    const int nt = blockIdx.x;                  // 0..11
    const int bm = blockIdx.y * 128;
    const int NITER = H_DIM / 32;               // 64

    float acc[4][8][4];                         // ni 0..3 gate, 4..7 up
#pragma unroll
    for (int mi = 0; mi < 4; mi++)
#pragma unroll
        for (int ni = 0; ni < 8; ni++)
#pragma unroll
            for (int v = 0; v < 4; v++) acc[mi][ni][v] = 0.f;

#pragma unroll
    for (int p = 0; p < PFD; p++) {
        g1_load_stage(sb + p * STAGE_BYTES, p * 32, bm, nt, A, W, tid);
        cp_commit();
    }

    const int arow = lane & 15;
    const int acol = (lane >> 4) * 16;
    const int brow = (lane & 7) + ((lane >> 4) << 3);
    const int bcol = ((lane >> 3) & 1) * 16;

    int s_it = 0, s_nx = PFD % NSTAGE;
    for (int it = 0; it < NITER; ++it) {
        cp_wait<PFD - 1>();
        __syncthreads();
        if (it + PFD < NITER) {
            g1_load_stage(sb + s_nx * STAGE_BYTES, (it + PFD) * 32, bm, nt, A, W, tid);
        }
        cp_commit();

        uint32_t SB = sb + s_it * STAGE_BYTES;
        s_it = (s_it == NSTAGE - 1) ? 0 : s_it + 1;
        s_nx = (s_nx == NSTAGE - 1) ? 0 : s_nx + 1;

        // hoist ALL fragment loads for both ks-blocks
        uint32_t bf[2][16];
        uint32_t af[2][4][4];
#pragma unroll
        for (int ks = 0; ks < 2; ks++) {
#pragma unroll
            for (int bq = 0; bq < 4; bq++) {
                uint32_t rb = SB + B_OFF + (warp_n * 64 + bq * 16 + brow) * ROWB
                            + ks * 32 + bcol;
                ldsm_x4(&bf[ks][bq * 4], rb);
            }
#pragma unroll
            for (int mi = 0; mi < 4; mi++) {
                uint32_t ra = SB + (warp_m * 64 + mi * 16 + arow) * ROWB + ks * 32 + acol;
                ldsm_x4(af[ks][mi], ra);
            }
        }
        // 64 MMAs, unbroken stream
#pragma unroll
        for (int ks = 0; ks < 2; ks++)
#pragma unroll
            for (int mi = 0; mi < 4; mi++)
#pragma unroll
                for (int ni = 0; ni < 8; ni++)
                    mma16816(acc[mi][ni], af[ks][mi], bf[ks][ni * 2], bf[ks][ni * 2 + 1]);
    }

    // epilogue: silu(gate)*up -> fp16 X (gate=acc[ni], up=acc[ni+4])
    const int g = lane >> 2, t = lane & 3;
#pragma unroll
    for (int mi = 0; mi < 4; mi++)
#pragma unroll
        for (int ni = 0; ni < 4; ni++) {
            int col = nt * 64 + warp_n * 32 + ni * 8 + t * 2;
            int row0 = bm + warp_m * 64 + mi * 16 + g;
#pragma unroll
            for (int h = 0; h < 2; h++) {
                int row = row0 + h * 8;
                float g0 = acc[mi][ni][h*2],     g1 = acc[mi][ni][h*2+1];
                float u0 = acc[mi][ni+4][h*2],   u1 = acc[mi][ni+4][h*2+1];
                float x0 = u0 * g0 / (1.0f + __expf(-g0));
                float x1 = u1 * g1 / (1.0f + __expf(-g1));
                *reinterpret_cast<uint32_t*>(X + (size_t)row * I_DIM + col) = pk2h(x0, x1);
            }
        }
}

// ============================================================================
// GEMM2: X[T,I] x Wd^T[H,I] -> out[T,H] fp32
// CTA: 128 thr, 4 warps (2m x 2n). Tile 128 x 128. Warp tile 64x64.
// ============================================================================
__device__ __forceinline__ void g2_load_stage(
    uint32_t SB, int k0, int bm, int bn,
    const __half* __restrict__ X, const __half* __restrict__ D, int tid)
{
#pragma unroll
    for (int c = tid; c < 512; c += 128) {
        int row = c >> 2, kc = c & 3;
        cp16(SB + row * ROWB + kc * 16,
             X + (size_t)(bm + row) * I_DIM + k0 + kc * 8);
    }
#pragma unroll
    for (int c = tid; c < 512; c += 128) {
        int row = c >> 2, kc = c & 3;
        cp16(SB + B_OFF + row * ROWB + kc * 16,
             D + (size_t)(bn + row) * I_DIM + k0 + kc * 8);
    }
}

__global__ __launch_bounds__(128, 2)
void gemm2_k(const __half* __restrict__ X, const __half* __restrict__ D,
             float* __restrict__ out)
{
    extern __shared__ char smem[];
    const uint32_t sb = smem_u32(smem);
    const int tid = threadIdx.x, wid = tid >> 5, lane = tid & 31;
    const int warp_m = wid & 1, warp_n = wid >> 1;
    const int bn = blockIdx.x * 128;
    const int bm = blockIdx.y * 128;
    const int NITER = I_DIM / 32;               // 24

    float acc[4][8][4];
#pragma unroll
    for (int mi = 0; mi < 4; mi++)
#pragma unroll
        for (int ni = 0; ni < 8; ni++)
#pragma unroll
            for (int v = 0; v < 4; v++) acc[mi][ni][v] = 0.f;

#pragma unroll
    for (int p = 0; p < PFD; p++) {
        g2_load_stage(sb + p * STAGE_BYTES, p * 32, bm, bn, X, D, tid);
        cp_commit();
    }

    const int arow = lane & 15;
    const int acol = (lane >> 4) * 16;
    const int brow = (lane & 7) + ((lane >> 4) << 3);
    const int bcol = ((lane >> 3) & 1) * 16;

    int s_it = 0, s_nx = PFD % NSTAGE;
    for (int it = 0; it < NITER; ++it) {
        cp_wait<PFD - 1>();
        __syncthreads();
        if (it + PFD < NITER) {
            g2_load_stage(sb + s_nx * STAGE_BYTES, (it + PFD) * 32, bm, bn, X, D, tid);
        }
        cp_commit();

        uint32_t SB = sb + s_it * STAGE_BYTES;
        s_it = (s_it == NSTAGE - 1) ? 0 : s_it + 1;
        s_nx = (s_nx == NSTAGE - 1) ? 0 : s_nx + 1;

        uint32_t bf[2][16];
        uint32_t af[2][4][4];
#pragma unroll
        for (int ks = 0; ks < 2; ks++) {
#pragma unroll
            for (int bq = 0; bq < 4; bq++) {
                uint32_t rb = SB + B_OFF + (warp_n * 64 + bq * 16 + brow) * ROWB
                            + ks * 32 + bcol;
                ldsm_x4(&bf[ks][bq * 4], rb);
            }
#pragma unroll
            for (int mi = 0; mi < 4; mi++) {
                uint32_t ra = SB + (warp_m * 64 + mi * 16 + arow) * ROWB + ks * 32 + acol;
                ldsm_x4(af[ks][mi], ra);
            }
        }
#pragma unroll
        for (int ks = 0; ks < 2; ks++)
#pragma unroll
            for (int mi = 0; mi < 4; mi++)
#pragma unroll
                for (int ni = 0; ni < 8; ni++)
                    mma16816(acc[mi][ni], af[ks][mi], bf[ks][ni * 2], bf[ks][ni * 2 + 1]);
    }

    const int g = lane >> 2, t = lane & 3;
#pragma unroll
    for (int mi = 0; mi < 4; mi++)
#pragma unroll
        for (int ni = 0; ni < 8; ni++) {
            int col = bn + warp_n * 64 + ni * 8 + t * 2;
            int row0 = bm + warp_m * 64 + mi * 16 + g;
            float2 v0 = make_float2(acc[mi][ni][0], acc[mi][ni][1]);
            float2 v1 = make_float2(acc[mi][ni][2], acc[mi][ni][3]);
            *reinterpret_cast<float2*>(out + (size_t)row0 * H_DIM + col) = v0;
            *reinterpret_cast<float2*>(out + (size_t)(row0 + 8) * H_DIM + col) = v1;
        }
}

// ---------------- prep kernels ----------------------------------------------
__global__ void conv_hidden_k(const float* __restrict__ in, __half* __restrict__ o)
{
    size_t i = (size_t)blockIdx.x * blockDim.x + threadIdx.x;
    float4 v = reinterpret_cast<const float4*>(in)[i];
    uint2 p;
    p.x = pk2h(v.x, v.y);
    p.y = pk2h(v.z, v.w);
    reinterpret_cast<uint2*>(o)[i] = p;
}

__global__ void transpose_conv_k(const float* __restrict__ in,
                                 __half* __restrict__ o, int R, int C)
{
    __shared__ float t[32][33];
    int bx = blockIdx.x * 32, by = blockIdx.y * 32;
    int tx = threadIdx.x, ty = threadIdx.y;
#pragma unroll
    for (int j = 0; j < 32; j += 8)
        t[ty + j][tx] = in[(size_t)(by + ty + j) * C + bx + tx];
    __syncthreads();
#pragma unroll
    for (int j = 0; j < 32; j += 8) {
        float a = t[tx][ty + j];
        o[(size_t)(bx + ty + j) * R + by + tx] = __float2half_rn(a);
    }
}

// ---------------- host ------------------------------------------------------
extern "C" void kernel_launch(void* const* d_in, const int* in_sizes, int n_in,
                              void* d_out, int out_size)
{
    const float* hidden = (const float*)d_in[0];   // [T, H]
    const float* wgu    = (const float*)d_in[1];   // [H, 2I]
    const float* wd     = (const float*)d_in[2];   // [I, H]
    float* out = (float*)d_out;                    // [T, H]

    __half *Ah, *W, *D, *X;
    cudaGetSymbolAddress((void**)&Ah, g_Ah);
    cudaGetSymbolAddress((void**)&W,  g_Wgu);
    cudaGetSymbolAddress((void**)&D,  g_Wd);
    cudaGetSymbolAddress((void**)&X,  g_X);

    cudaFuncSetAttribute(gemm1_k, cudaFuncAttributeMaxDynamicSharedMemorySize, SMEM_BYTES);
    cudaFuncSetAttribute(gemm2_k, cudaFuncAttributeMaxDynamicSharedMemorySize, SMEM_BYTES);

    conv_hidden_k<<<(int)(((size_t)T_TOK * H_DIM / 4) / 256), 256>>>(hidden, Ah);
    transpose_conv_k<<<dim3(2 * I_DIM / 32, H_DIM / 32), dim3(32, 8)>>>(wgu, W, H_DIM, 2 * I_DIM);
    transpose_conv_k<<<dim3(H_DIM / 32, I_DIM / 32), dim3(32, 8)>>>(wd, D, I_DIM, H_DIM);

    gemm1_k<<<dim3(I_DIM / 64, T_TOK / 128), 128, SMEM_BYTES>>>(Ah, W, X);
    gemm2_k<<<dim3(H_DIM / 128, T_TOK / 128), 128, SMEM_BYTES>>>(X, D, out);
}

// round 14
// speedup vs baseline: 3.4014x; 1.1396x over previous
#include <cuda_runtime.h>
#include <cuda_fp16.h>
#include <cstdint>

#define T_TOK 32768
#define H_DIM 2048
#define I_DIM 768

// ---------------- static device scratch (fp16) ------------------------------
__device__ __half g_Ah[(size_t)T_TOK * H_DIM];          // hidden   [T,H]
__device__ __half g_Wgu[(size_t)2 * I_DIM * H_DIM];     // w_gate_up^T [2I,H]
__device__ __half g_Wd[(size_t)H_DIM * I_DIM];          // w_down^T    [H,I]
__device__ __half g_X[(size_t)T_TOK * I_DIM];           // silu(g)*u   [T,I]

// ---------------- helpers ----------------------------------------------------
__device__ __forceinline__ uint32_t smem_u32(const void* p) {
    return (uint32_t)__cvta_generic_to_shared(p);
}
__device__ __forceinline__ void cp16(uint32_t dst, const void* src) {
    asm volatile("cp.async.cg.shared.global [%0], [%1], 16;" :: "r"(dst), "l"(src));
}
__device__ __forceinline__ void cp_commit() {
    asm volatile("cp.async.commit_group;" ::: "memory");
}
template <int N>
__device__ __forceinline__ void cp_wait() {
    asm volatile("cp.async.wait_group %0;" :: "n"(N) : "memory");
}
__device__ __forceinline__ void ldsm_x4(uint32_t* r, uint32_t addr) {
    asm volatile("ldmatrix.sync.aligned.m8n8.x4.shared.b16 {%0,%1,%2,%3}, [%4];"
                 : "=r"(r[0]), "=r"(r[1]), "=r"(r[2]), "=r"(r[3]) : "r"(addr));
}
__device__ __forceinline__ void mma16816(float* d, const uint32_t* a,
                                         uint32_t b0, uint32_t b1) {
    asm volatile(
        "mma.sync.aligned.m16n8k16.row.col.f32.f16.f16.f32 "
        "{%0,%1,%2,%3}, {%4,%5,%6,%7}, {%8,%9}, {%0,%1,%2,%3};"
        : "+f"(d[0]), "+f"(d[1]), "+f"(d[2]), "+f"(d[3])
        : "r"(a[0]), "r"(a[1]), "r"(a[2]), "r"(a[3]), "r"(b0), "r"(b1));
}
__device__ __forceinline__ uint32_t pk2h(float a, float b) {
    __half2 t = __floats2half2_rn(a, b);
    return *reinterpret_cast<uint32_t*>(&t);
}

// SMEM stage: rows of 32 fp16 = 64B data + 16B pad -> stride 80B (20 words).
// 8-row ldmatrix bank starts (r*20)%32 = {0,20,8,28,16,4,24,12}: conflict-free.
//   A tile (128 rows) @0, B tile (128 rows) @10240
#define ROWB        80
#define B_OFF       10240
#define STAGE_BYTES 20480
#define NSTAGE      5
#define PFD         4
#define SMEM_BYTES  (NSTAGE * STAGE_BYTES)

// load one ks-block of fragments (A: 4 x ldsm.x4, B: 4 x ldsm.x4)
__device__ __forceinline__ void load_frags(
    uint32_t SB, int ks, int warp_m, int warp_n,
    int arow, int acol, int brow, int bcol,
    uint32_t af[4][4], uint32_t bf[16])
{
#pragma unroll
    for (int bq = 0; bq < 4; bq++) {
        uint32_t rb = SB + B_OFF + (warp_n * 64 + bq * 16 + brow) * ROWB
                    + ks * 32 + bcol;
        ldsm_x4(&bf[bq * 4], rb);
    }
#pragma unroll
    for (int mi = 0; mi < 4; mi++) {
        uint32_t ra = SB + (warp_m * 64 + mi * 16 + arow) * ROWB + ks * 32 + acol;
        ldsm_x4(af[mi], ra);
    }
}

// ============================================================================
// GEMM1: hidden[T,H] x Wgu^T[2I,H] -> silu(gate)*up -> X[T,I] fp16
// CTA: 128 thr, 4 warps (2m x 2n). CTA tile 128 tokens x 64 I-cols.
// Warp tile 64x64. Cross-iteration fragment pipelining, barrier mid-iter.
// ============================================================================
__device__ __forceinline__ void g1_load_stage(
    uint32_t SB, int k0, int bm, int nt,
    const __half* __restrict__ A, const __half* __restrict__ W, int tid)
{
#pragma unroll
    for (int c = tid; c < 512; c += 128) {            // A: 128 rows x 4 x 16B
        int row = c >> 2, kc = c & 3;
        cp16(SB + row * ROWB + kc * 16,
             A + (size_t)(bm + row) * H_DIM + k0 + kc * 8);
    }
#pragma unroll
    for (int c = tid; c < 512; c += 128) {            // B: interleaved gate/up
        int row = c >> 2, kc = c & 3;
        int wn = row >> 6, r = row & 63;
        int gr = (r < 32) ? (nt * 64 + wn * 32 + r)
                          : (I_DIM + nt * 64 + wn * 32 + r - 32);
        cp16(SB + B_OFF + row * ROWB + kc * 16,
             W + (size_t)gr * H_DIM + k0 + kc * 8);
    }
}

__global__ __launch_bounds__(128, 2)
void gemm1_k(const __half* __restrict__ A, const __half* __restrict__ W,
             __half* __restrict__ X)
{
    extern __shared__ char smem[];
    const uint32_t sb = smem_u32(smem);
    const int tid = threadIdx.x, wid = tid >> 5, lane = tid & 31;
    const int warp_m = wid & 1, warp_n = wid >> 1;
    const int nt = blockIdx.x;                  // 0..11
    const int bm = blockIdx.y * 128;
    const int NITER = H_DIM / 32;               // 64

    float acc[4][8][4];                         // ni 0..3 gate, 4..7 up
#pragma unroll
    for (int mi = 0; mi < 4; mi++)
#pragma unroll
        for (int ni = 0; ni < 8; ni++)
#pragma unroll
            for (int v = 0; v < 4; v++) acc[mi][ni][v] = 0.f;

#pragma unroll
    for (int p = 0; p < PFD; p++) {
        g1_load_stage(sb + p * STAGE_BYTES, p * 32, bm, nt, A, W, tid);
        cp_commit();
    }

    const int arow = lane & 15;
    const int acol = (lane >> 4) * 16;
    const int brow = (lane & 7) + ((lane >> 4) << 3);
    const int bcol = ((lane >> 3) & 1) * 16;

    uint32_t af0[4][4], bf0[16], af1[4][4], bf1[16];

    cp_wait<PFD - 1>();
    __syncthreads();
    load_frags(sb, 0, warp_m, warp_n, arow, acol, brow, bcol, af0, bf0);

    int s_it = 0, s_nx = PFD % NSTAGE;
    for (int it = 0; it < NITER; ++it) {
        uint32_t SBc = sb + s_it * STAGE_BYTES;
        int s_n1 = (s_it == NSTAGE - 1) ? 0 : s_it + 1;
        uint32_t SBn = sb + s_n1 * STAGE_BYTES;

        // prefetch gmem -> smem (writes stage it+PFD mod 5; its last reader
        // finished before LAST iteration's mid-barrier)
        if (it + PFD < NITER) {
            g1_load_stage(sb + s_nx * STAGE_BYTES, (it + PFD) * 32, bm, nt, A, W, tid);
        }
        cp_commit();

        // ks1 frags from CURRENT stage (visible since last iter's barrier)
        load_frags(SBc, 1, warp_m, warp_n, arow, acol, brow, bcol, af1, bf1);

        // MMA ks0
#pragma unroll
        for (int mi = 0; mi < 4; mi++)
#pragma unroll
            for (int ni = 0; ni < 8; ni++)
                mma16816(acc[mi][ni], af0[mi], bf0[ni * 2], bf0[ni * 2 + 1]);

        // make stage it+1 visible to ALL threads, then read its ks0 frags
        cp_wait<PFD - 1>();
        __syncthreads();
        if (it + 1 < NITER) {
            load_frags(SBn, 0, warp_m, warp_n, arow, acol, brow, bcol, af0, bf0);
        }

        // MMA ks1
#pragma unroll
        for (int mi = 0; mi < 4; mi++)
#pragma unroll
            for (int ni = 0; ni < 8; ni++)
                mma16816(acc[mi][ni], af1[mi], bf1[ni * 2], bf1[ni * 2 + 1]);

        s_it = s_n1;
        s_nx = (s_nx == NSTAGE - 1) ? 0 : s_nx + 1;
    }

    // epilogue: silu(gate)*up -> fp16 X (gate=acc[ni], up=acc[ni+4])
    const int g = lane >> 2, t = lane & 3;
#pragma unroll
    for (int mi = 0; mi < 4; mi++)
#pragma unroll
        for (int ni = 0; ni < 4; ni++) {
            int col = nt * 64 + warp_n * 32 + ni * 8 + t * 2;
            int row0 = bm + warp_m * 64 + mi * 16 + g;
#pragma unroll
            for (int h = 0; h < 2; h++) {
                int row = row0 + h * 8;
                float g0 = acc[mi][ni][h*2],     g1 = acc[mi][ni][h*2+1];
                float u0 = acc[mi][ni+4][h*2],   u1 = acc[mi][ni+4][h*2+1];
                float x0 = u0 * g0 / (1.0f + __expf(-g0));
                float x1 = u1 * g1 / (1.0f + __expf(-g1));
                *reinterpret_cast<uint32_t*>(X + (size_t)row * I_DIM + col) = pk2h(x0, x1);
            }
        }
}

// ============================================================================
// GEMM2: X[T,I] x Wd^T[H,I] -> out[T,H] fp32
// CTA: 128 thr, 4 warps (2m x 2n). Tile 128 x 128. Warp tile 64x64.
// ============================================================================
__device__ __forceinline__ void g2_load_stage(
    uint32_t SB, int k0, int bm, int bn,
    const __half* __restrict__ X, const __half* __restrict__ D, int tid)
{
#pragma unroll
    for (int c = tid; c < 512; c += 128) {
        int row = c >> 2, kc = c & 3;
        cp16(SB + row * ROWB + kc * 16,
             X + (size_t)(bm + row) * I_DIM + k0 + kc * 8);
    }
#pragma unroll
    for (int c = tid; c < 512; c += 128) {
        int row = c >> 2, kc = c & 3;
        cp16(SB + B_OFF + row * ROWB + kc * 16,
             D + (size_t)(bn + row) * I_DIM + k0 + kc * 8);
    }
}

__global__ __launch_bounds__(128, 2)
void gemm2_k(const __half* __restrict__ X, const __half* __restrict__ D,
             float* __restrict__ out)
{
    extern __shared__ char smem[];
    const uint32_t sb = smem_u32(smem);
    const int tid = threadIdx.x, wid = tid >> 5, lane = tid & 31;
    const int warp_m = wid & 1, warp_n = wid >> 1;
    const int bn = blockIdx.x * 128;
    const int bm = blockIdx.y * 128;
    const int NITER = I_DIM / 32;               // 24

    float acc[4][8][4];
#pragma unroll
    for (int mi = 0; mi < 4; mi++)
#pragma unroll
        for (int ni = 0; ni < 8; ni++)
#pragma unroll
            for (int v = 0; v < 4; v++) acc[mi][ni][v] = 0.f;

#pragma unroll
    for (int p = 0; p < PFD; p++) {
        g2_load_stage(sb + p * STAGE_BYTES, p * 32, bm, bn, X, D, tid);
        cp_commit();
    }

    const int arow = lane & 15;
    const int acol = (lane >> 4) * 16;
    const int brow = (lane & 7) + ((lane >> 4) << 3);
    const int bcol = ((lane >> 3) & 1) * 16;

    uint32_t af0[4][4], bf0[16], af1[4][4], bf1[16];

    cp_wait<PFD - 1>();
    __syncthreads();
    load_frags(sb, 0, warp_m, warp_n, arow, acol, brow, bcol, af0, bf0);

    int s_it = 0, s_nx = PFD % NSTAGE;
    for (int it = 0; it < NITER; ++it) {
        uint32_t SBc = sb + s_it * STAGE_BYTES;
        int s_n1 = (s_it == NSTAGE - 1) ? 0 : s_it + 1;
        uint32_t SBn = sb + s_n1 * STAGE_BYTES;

        if (it + PFD < NITER) {
            g2_load_stage(sb + s_nx * STAGE_BYTES, (it + PFD) * 32, bm, bn, X, D, tid);
        }
        cp_commit();

        load_frags(SBc, 1, warp_m, warp_n, arow, acol, brow, bcol, af1, bf1);

#pragma unroll
        for (int mi = 0; mi < 4; mi++)
#pragma unroll
            for (int ni = 0; ni < 8; ni++)
                mma16816(acc[mi][ni], af0[mi], bf0[ni * 2], bf0[ni * 2 + 1]);

        cp_wait<PFD - 1>();
        __syncthreads();
        if (it + 1 < NITER) {
            load_frags(SBn, 0, warp_m, warp_n, arow, acol, brow, bcol, af0, bf0);
        }

#pragma unroll
        for (int mi = 0; mi < 4; mi++)
#pragma unroll
            for (int ni = 0; ni < 8; ni++)
                mma16816(acc[mi][ni], af1[mi], bf1[ni * 2], bf1[ni * 2 + 1]);

        s_it = s_n1;
        s_nx = (s_nx == NSTAGE - 1) ? 0 : s_nx + 1;
    }

    const int g = lane >> 2, t = lane & 3;
#pragma unroll
    for (int mi = 0; mi < 4; mi++)
#pragma unroll
        for (int ni = 0; ni < 8; ni++) {
            int col = bn + warp_n * 64 + ni * 8 + t * 2;
            int row0 = bm + warp_m * 64 + mi * 16 + g;
            float2 v0 = make_float2(acc[mi][ni][0], acc[mi][ni][1]);
            float2 v1 = make_float2(acc[mi][ni][2], acc[mi][ni][3]);
            *reinterpret_cast<float2*>(out + (size_t)row0 * H_DIM + col) = v0;
            *reinterpret_cast<float2*>(out + (size_t)(row0 + 8) * H_DIM + col) = v1;
        }
}

// ---------------- prep kernels ----------------------------------------------
__global__ void conv_hidden_k(const float* __restrict__ in, __half* __restrict__ o)
{
    size_t i = (size_t)blockIdx.x * blockDim.x + threadIdx.x;
    float4 v = reinterpret_cast<const float4*>(in)[i];
    uint2 p;
    p.x = pk2h(v.x, v.y);
    p.y = pk2h(v.z, v.w);
    reinterpret_cast<uint2*>(o)[i] = p;
}

__global__ void transpose_conv_k(const float* __restrict__ in,
                                 __half* __restrict__ o, int R, int C)
{
    __shared__ float t[32][33];
    int bx = blockIdx.x * 32, by = blockIdx.y * 32;
    int tx = threadIdx.x, ty = threadIdx.y;
#pragma unroll
    for (int j = 0; j < 32; j += 8)
        t[ty + j][tx] = in[(size_t)(by + ty + j) * C + bx + tx];
    __syncthreads();
#pragma unroll
    for (int j = 0; j < 32; j += 8) {
        float a = t[tx][ty + j];
        o[(size_t)(bx + ty + j) * R + by + tx] = __float2half_rn(a);
    }
}

// ---------------- host ------------------------------------------------------
extern "C" void kernel_launch(void* const* d_in, const int* in_sizes, int n_in,
                              void* d_out, int out_size)
{
    const float* hidden = (const float*)d_in[0];   // [T, H]
    const float* wgu    = (const float*)d_in[1];   // [H, 2I]
    const float* wd     = (const float*)d_in[2];   // [I, H]
    float* out = (float*)d_out;                    // [T, H]

    __half *Ah, *W, *D, *X;
    cudaGetSymbolAddress((void**)&Ah, g_Ah);
    cudaGetSymbolAddress((void**)&W,  g_Wgu);
    cudaGetSymbolAddress((void**)&D,  g_Wd);
    cudaGetSymbolAddress((void**)&X,  g_X);

    cudaFuncSetAttribute(gemm1_k, cudaFuncAttributeMaxDynamicSharedMemorySize, SMEM_BYTES);
    cudaFuncSetAttribute(gemm2_k, cudaFuncAttributeMaxDynamicSharedMemorySize, SMEM_BYTES);

    conv_hidden_k<<<(int)(((size_t)T_TOK * H_DIM / 4) / 256), 256>>>(hidden, Ah);
    transpose_conv_k<<<dim3(2 * I_DIM / 32, H_DIM / 32), dim3(32, 8)>>>(wgu, W, H_DIM, 2 * I_DIM);
    transpose_conv_k<<<dim3(H_DIM / 32, I_DIM / 32), dim3(32, 8)>>>(wd, D, I_DIM, H_DIM);

    gemm1_k<<<dim3(I_DIM / 64, T_TOK / 128), 128, SMEM_BYTES>>>(Ah, W, X);
    gemm2_k<<<dim3(H_DIM / 128, T_TOK / 128), 128, SMEM_BYTES>>>(X, D, out);
}